// round 1
// baseline (speedup 1.0000x reference)
#include <cuda_runtime.h>
#include <math.h>

// Problem constants
#define BH    32        // B*H
#define SEQ   2048
#define HD    64
#define BM    64        // q-rows per block
#define BN    64        // k-rows per tile
#define NTHR  256

// smem layout (floats)
#define QS_STRIDE 68            // 64 + 4 pad (bank spread, keeps 16B alignment: 272B rows)
#define SS_STRIDE 65
#define SMEM_FLOATS (BM*QS_STRIDE + HD*BN + BN*HD + BM*SS_STRIDE)
#define SMEM_BYTES  (SMEM_FLOATS * 4)

__global__ void init_amax_kernel(float* tail) {
    tail[0] = 0.0f;   // amax_s
    tail[1] = 0.0f;   // amax_o
}

__device__ __forceinline__ void atomic_max_pos(float* addr, float v) {
    // valid for non-negative floats: uint compare == float compare
    atomicMax(reinterpret_cast<unsigned int*>(addr), __float_as_uint(v));
}

__global__ __launch_bounds__(NTHR) void flash_fwd_kernel(
    const float* __restrict__ q, const float* __restrict__ k, const float* __restrict__ v,
    const float* __restrict__ dsq, const float* __restrict__ dsk, const float* __restrict__ dsv,
    const float* __restrict__ qss, const float* __restrict__ qso, const float* __restrict__ dss,
    float* __restrict__ out, float* __restrict__ amax_tail)
{
    extern __shared__ float sm[];
    float* Qs = sm;                          // [BM][QS_STRIDE]
    float* Kt = Qs + BM * QS_STRIDE;         // [HD][BN]  (d-major)
    float* Vs = Kt + HD * BN;                // [BN][HD]
    float* Ss = Vs + BN * HD;                // [BM][SS_STRIDE]

    const int qt = blockIdx.x;               // q tile index 0..31
    const int bh = blockIdx.y;               // 0..31
    const int t  = threadIdx.x;
    const int r  = t >> 2;                   // row within tile 0..63
    const int cg = t & 3;                    // column group 0..3
    const int col0 = cg * 16;

    const float qk_scale = dsq[0] * dsk[0] * 0.125f;           // 1/sqrt(64)
    const float pv_scale = qss[0] * dss[0] * dsv[0];
    const float o_scale  = qso[0];

    const size_t base = (size_t)bh * SEQ * HD;
    const int q0 = qt * BM;

    // ---- load Q tile (64x64) into padded smem ----
    for (int i = t; i < BM * (HD / 4); i += NTHR) {
        int row = i >> 4, d4 = i & 15;
        float4 val = *(const float4*)(q + base + (size_t)(q0 + row) * HD + d4 * 4);
        *(float4*)(Qs + row * QS_STRIDE + d4 * 4) = val;
    }

    float o_acc[16];
    #pragma unroll
    for (int c = 0; c < 16; c++) o_acc[c] = 0.0f;
    float m_run = -1e30f;
    float l_run = 0.0f;

    for (int kt = 0; kt <= qt; kt++) {
        const int n0 = kt * BN;
        __syncthreads();                               // protect Kt/Vs reuse from prev iter
        // ---- load K tile transposed (d-major) and V tile ----
        for (int i = t; i < BN * (HD / 4); i += NTHR) {
            int row = i >> 4, d4 = i & 15;
            float4 kk = *(const float4*)(k + base + (size_t)(n0 + row) * HD + d4 * 4);
            Kt[(d4 * 4 + 0) * BN + row] = kk.x;
            Kt[(d4 * 4 + 1) * BN + row] = kk.y;
            Kt[(d4 * 4 + 2) * BN + row] = kk.z;
            Kt[(d4 * 4 + 3) * BN + row] = kk.w;
            float4 vv = *(const float4*)(v + base + (size_t)(n0 + row) * HD + d4 * 4);
            *(float4*)(Vs + row * HD + d4 * 4) = vv;
        }
        __syncthreads();

        // ---- S = Q K^T (each thread: 1 row x 16 cols) ----
        float s[16];
        #pragma unroll
        for (int c = 0; c < 16; c++) s[c] = 0.0f;
        #pragma unroll 4
        for (int d = 0; d < HD; d++) {
            const float qv = Qs[r * QS_STRIDE + d];
            const float* kp = Kt + d * BN + col0;
            #pragma unroll
            for (int c = 0; c < 16; c++) s[c] = fmaf(qv, kp[c], s[c]);
        }
        #pragma unroll
        for (int c = 0; c < 16; c++) s[c] *= qk_scale;

        // ---- causal mask on diagonal tile ----
        if (kt == qt) {
            const int qi = q0 + r;
            #pragma unroll
            for (int c = 0; c < 16; c++)
                if (n0 + col0 + c > qi) s[c] = -1e30f;
        }

        // ---- online softmax (reduce over 4 lanes of the row group) ----
        float tmax = -1e30f;
        #pragma unroll
        for (int c = 0; c < 16; c++) tmax = fmaxf(tmax, s[c]);
        tmax = fmaxf(tmax, __shfl_xor_sync(0xffffffffu, tmax, 1));
        tmax = fmaxf(tmax, __shfl_xor_sync(0xffffffffu, tmax, 2));
        const float m_new = fmaxf(m_run, tmax);
        const float alpha = __expf(m_run - m_new);

        float lsum = 0.0f;
        #pragma unroll
        for (int c = 0; c < 16; c++) {
            float p = __expf(s[c] - m_new);
            s[c] = p;
            lsum += p;
        }
        lsum += __shfl_xor_sync(0xffffffffu, lsum, 1);
        lsum += __shfl_xor_sync(0xffffffffu, lsum, 2);
        l_run = l_run * alpha + lsum;
        m_run = m_new;

        #pragma unroll
        for (int c = 0; c < 16; c++) o_acc[c] *= alpha;

        // ---- stage P through smem for the PV GEMM ----
        #pragma unroll
        for (int c = 0; c < 16; c++) Ss[r * SS_STRIDE + col0 + c] = s[c];
        __syncthreads();

        // ---- O += P V (each thread: 1 row x 16 dims) ----
        #pragma unroll 4
        for (int n = 0; n < BN; n++) {
            const float pv = Ss[r * SS_STRIDE + n];
            const float* vp = Vs + n * HD + col0;
            #pragma unroll
            for (int c = 0; c < 16; c++) o_acc[c] = fmaf(pv, vp[c], o_acc[c]);
        }
    }

    // ---- epilogue: normalize, fold scales, amax, store ----
    const float inv_l = 1.0f / l_run;
    float amax_s_loc = inv_l;                 // max softmax prob of this row = 1/l
    float amax_o_loc = 0.0f;
    const size_t orow = base + (size_t)(q0 + r) * HD + col0;
    #pragma unroll
    for (int c = 0; c < 16; c++) {
        float o_raw = o_acc[c] * inv_l * pv_scale;
        amax_o_loc = fmaxf(amax_o_loc, fabsf(o_raw));
        out[orow + c] = o_raw * o_scale;
    }

    // ---- block-level amax reduction -> 1 atomic pair per block ----
    amax_s_loc = fmaxf(amax_s_loc, __shfl_xor_sync(0xffffffffu, amax_s_loc, 16));
    amax_s_loc = fmaxf(amax_s_loc, __shfl_xor_sync(0xffffffffu, amax_s_loc, 8));
    amax_s_loc = fmaxf(amax_s_loc, __shfl_xor_sync(0xffffffffu, amax_s_loc, 4));
    amax_s_loc = fmaxf(amax_s_loc, __shfl_xor_sync(0xffffffffu, amax_s_loc, 2));
    amax_s_loc = fmaxf(amax_s_loc, __shfl_xor_sync(0xffffffffu, amax_s_loc, 1));
    amax_o_loc = fmaxf(amax_o_loc, __shfl_xor_sync(0xffffffffu, amax_o_loc, 16));
    amax_o_loc = fmaxf(amax_o_loc, __shfl_xor_sync(0xffffffffu, amax_o_loc, 8));
    amax_o_loc = fmaxf(amax_o_loc, __shfl_xor_sync(0xffffffffu, amax_o_loc, 4));
    amax_o_loc = fmaxf(amax_o_loc, __shfl_xor_sync(0xffffffffu, amax_o_loc, 2));
    amax_o_loc = fmaxf(amax_o_loc, __shfl_xor_sync(0xffffffffu, amax_o_loc, 1));

    __syncthreads();                // Ss no longer needed; reuse as scratch
    const int wid = t >> 5;
    if ((t & 31) == 0) {
        Ss[wid] = amax_s_loc;
        Ss[8 + wid] = amax_o_loc;
    }
    __syncthreads();
    if (t == 0) {
        float as = Ss[0], ao = Ss[8];
        #pragma unroll
        for (int w = 1; w < 8; w++) { as = fmaxf(as, Ss[w]); ao = fmaxf(ao, Ss[8 + w]); }
        atomic_max_pos(&amax_tail[0], as);
        atomic_max_pos(&amax_tail[1], ao);
    }
}

extern "C" void kernel_launch(void* const* d_in, const int* in_sizes, int n_in,
                              void* d_out, int out_size) {
    const float* q   = (const float*)d_in[0];
    const float* k   = (const float*)d_in[1];
    const float* v   = (const float*)d_in[2];
    const float* dsq = (const float*)d_in[3];
    const float* dsk = (const float*)d_in[4];
    const float* dsv = (const float*)d_in[5];
    const float* qss = (const float*)d_in[6];
    const float* qso = (const float*)d_in[7];
    const float* dss = (const float*)d_in[8];
    float* out = (float*)d_out;

    const int n_o = out_size - 2;            // o elements; tail = {amax_s, amax_o}
    float* tail = out + n_o;

    cudaFuncSetAttribute(flash_fwd_kernel,
                         cudaFuncAttributeMaxDynamicSharedMemorySize, SMEM_BYTES);

    init_amax_kernel<<<1, 1>>>(tail);

    dim3 grid(SEQ / BM, BH);                 // (32, 32)
    flash_fwd_kernel<<<grid, NTHR, SMEM_BYTES>>>(q, k, v, dsq, dsk, dsv, qss, qso, dss,
                                                 out, tail);
}

// round 2
// speedup vs baseline: 3.3729x; 3.3729x over previous
#include <cuda_runtime.h>
#include <math.h>

#define BH    32
#define SEQ   2048
#define HD    64
#define BM    128       // q-rows per block
#define BN    64        // k-rows per tile
#define NTHR  256

// smem strides (floats) — padded to rotate bank starts, multiples of 4 for LDS.128
#define QT_STRIDE 132   // Qt[HD][BM+4]   (d-major Q)
#define KT_STRIDE 68    // Kt[HD][BN+4]   (d-major K)
#define VS_STRIDE 64    // Vs[BN][HD]
#define PT_STRIDE 132   // Pt[BN][BM+4]   (row-major-in-n transposed P)

#define SMEM_FLOATS (HD*QT_STRIDE + HD*KT_STRIDE + BN*VS_STRIDE + BN*PT_STRIDE)
#define SMEM_BYTES  (SMEM_FLOATS * 4)

__global__ void init_amax_kernel(float* tail) {
    tail[0] = 0.0f;
    tail[1] = 0.0f;
}

__device__ __forceinline__ void atomic_max_pos(float* addr, float v) {
    atomicMax(reinterpret_cast<unsigned int*>(addr), __float_as_uint(v));
}

__global__ __launch_bounds__(NTHR) void flash_fwd_kernel(
    const float* __restrict__ q, const float* __restrict__ k, const float* __restrict__ v,
    const float* __restrict__ dsq, const float* __restrict__ dsk, const float* __restrict__ dsv,
    const float* __restrict__ qss, const float* __restrict__ qso, const float* __restrict__ dss,
    float* __restrict__ out, float* __restrict__ amax_tail)
{
    extern __shared__ float sm[];
    float* Qt = sm;                         // [HD][QT_STRIDE]
    float* Kt = Qt + HD * QT_STRIDE;        // [HD][KT_STRIDE]
    float* Vs = Kt + HD * KT_STRIDE;        // [BN][VS_STRIDE]
    float* Pt = Vs + BN * VS_STRIDE;        // [BN][PT_STRIDE]

    const int qt = (gridDim.x - 1) - blockIdx.x;   // heavy tiles first
    const int bh = blockIdx.y;
    const int t  = threadIdx.x;
    const int tx = t & 15;                  // col group: cols tx*4..+3
    const int ty = t >> 4;                  // row group: rows ty*8..+7

    const float qk_scale = dsq[0] * dsk[0] * 0.125f;     // 1/sqrt(64)
    const float pv_scale = qss[0] * dss[0] * dsv[0];
    const float o_scale  = qso[0];

    const size_t base = (size_t)bh * SEQ * HD;
    const int q0 = qt * BM;

    // ---- load Q tile (BM x 64), store transposed d-major ----
    for (int i = t; i < BM * (HD / 4); i += NTHR) {
        int row = i >> 4, d4 = i & 15;
        float4 val = *(const float4*)(q + base + (size_t)(q0 + row) * HD + d4 * 4);
        Qt[(d4 * 4 + 0) * QT_STRIDE + row] = val.x;
        Qt[(d4 * 4 + 1) * QT_STRIDE + row] = val.y;
        Qt[(d4 * 4 + 2) * QT_STRIDE + row] = val.z;
        Qt[(d4 * 4 + 3) * QT_STRIDE + row] = val.w;
    }

    float oacc[8][4];
    #pragma unroll
    for (int i = 0; i < 8; i++)
        #pragma unroll
        for (int j = 0; j < 4; j++) oacc[i][j] = 0.0f;
    float m_run[8], l_run[8];
    #pragma unroll
    for (int i = 0; i < 8; i++) { m_run[i] = -1e30f; l_run[i] = 0.0f; }

    const int n_tiles = (q0 + BM) / BN;     // tiles 0..2qt+1
    for (int kt = 0; kt < n_tiles; kt++) {
        const int n0 = kt * BN;
        __syncthreads();                    // prev PV done before Kt/Vs overwrite
        for (int i = t; i < BN * (HD / 4); i += NTHR) {
            int row = i >> 4, d4 = i & 15;
            float4 kk = *(const float4*)(k + base + (size_t)(n0 + row) * HD + d4 * 4);
            Kt[(d4 * 4 + 0) * KT_STRIDE + row] = kk.x;
            Kt[(d4 * 4 + 1) * KT_STRIDE + row] = kk.y;
            Kt[(d4 * 4 + 2) * KT_STRIDE + row] = kk.z;
            Kt[(d4 * 4 + 3) * KT_STRIDE + row] = kk.w;
            float4 vv = *(const float4*)(v + base + (size_t)(n0 + row) * HD + d4 * 4);
            *(float4*)(Vs + row * VS_STRIDE + d4 * 4) = vv;
        }
        __syncthreads();

        // ---- S = Q K^T : 8x4 outer-product per thread ----
        float s[8][4];
        #pragma unroll
        for (int i = 0; i < 8; i++)
            #pragma unroll
            for (int j = 0; j < 4; j++) s[i][j] = 0.0f;

        #pragma unroll 2
        for (int d = 0; d < HD; d++) {
            const float4 a0 = *(const float4*)(Qt + d * QT_STRIDE + ty * 8);
            const float4 a1 = *(const float4*)(Qt + d * QT_STRIDE + ty * 8 + 4);
            const float4 bb = *(const float4*)(Kt + d * KT_STRIDE + tx * 4);
            const float a[8] = {a0.x, a0.y, a0.z, a0.w, a1.x, a1.y, a1.z, a1.w};
            const float b[4] = {bb.x, bb.y, bb.z, bb.w};
            #pragma unroll
            for (int i = 0; i < 8; i++)
                #pragma unroll
                for (int j = 0; j < 4; j++)
                    s[i][j] = fmaf(a[i], b[j], s[i][j]);
        }
        #pragma unroll
        for (int i = 0; i < 8; i++)
            #pragma unroll
            for (int j = 0; j < 4; j++) s[i][j] *= qk_scale;

        // ---- causal mask (only needed on last two tiles) ----
        if (n0 + BN - 1 > q0) {
            #pragma unroll
            for (int i = 0; i < 8; i++) {
                const int qi = q0 + ty * 8 + i;
                #pragma unroll
                for (int j = 0; j < 4; j++)
                    if (n0 + tx * 4 + j > qi) s[i][j] = -1e30f;
            }
        }

        // ---- online softmax (rows reduced over the 16 tx lanes) ----
        #pragma unroll
        for (int i = 0; i < 8; i++) {
            float mx = fmaxf(fmaxf(s[i][0], s[i][1]), fmaxf(s[i][2], s[i][3]));
            mx = fmaxf(mx, __shfl_xor_sync(0xffffffffu, mx, 1));
            mx = fmaxf(mx, __shfl_xor_sync(0xffffffffu, mx, 2));
            mx = fmaxf(mx, __shfl_xor_sync(0xffffffffu, mx, 4));
            mx = fmaxf(mx, __shfl_xor_sync(0xffffffffu, mx, 8));
            const float m_new = fmaxf(m_run[i], mx);
            const float alpha = __expf(m_run[i] - m_new);
            float sum = 0.0f;
            #pragma unroll
            for (int j = 0; j < 4; j++) {
                float p = __expf(s[i][j] - m_new);
                s[i][j] = p;
                sum += p;
            }
            sum += __shfl_xor_sync(0xffffffffu, sum, 1);
            sum += __shfl_xor_sync(0xffffffffu, sum, 2);
            sum += __shfl_xor_sync(0xffffffffu, sum, 4);
            sum += __shfl_xor_sync(0xffffffffu, sum, 8);
            l_run[i] = l_run[i] * alpha + sum;
            m_run[i] = m_new;
            #pragma unroll
            for (int j = 0; j < 4; j++) oacc[i][j] *= alpha;
        }

        // ---- stage P transposed: Pt[n][row] ----
        #pragma unroll
        for (int j = 0; j < 4; j++) {
            float4 lo = make_float4(s[0][j], s[1][j], s[2][j], s[3][j]);
            float4 hi = make_float4(s[4][j], s[5][j], s[6][j], s[7][j]);
            *(float4*)(Pt + (tx * 4 + j) * PT_STRIDE + ty * 8)     = lo;
            *(float4*)(Pt + (tx * 4 + j) * PT_STRIDE + ty * 8 + 4) = hi;
        }
        __syncthreads();

        // ---- O += P V : 8x4 outer-product per thread ----
        #pragma unroll 2
        for (int n = 0; n < BN; n++) {
            const float4 p0 = *(const float4*)(Pt + n * PT_STRIDE + ty * 8);
            const float4 p1 = *(const float4*)(Pt + n * PT_STRIDE + ty * 8 + 4);
            const float4 vv = *(const float4*)(Vs + n * VS_STRIDE + tx * 4);
            const float a[8] = {p0.x, p0.y, p0.z, p0.w, p1.x, p1.y, p1.z, p1.w};
            const float b[4] = {vv.x, vv.y, vv.z, vv.w};
            #pragma unroll
            for (int i = 0; i < 8; i++)
                #pragma unroll
                for (int j = 0; j < 4; j++)
                    oacc[i][j] = fmaf(a[i], b[j], oacc[i][j]);
        }
    }

    // ---- epilogue ----
    float amax_s_loc = 0.0f, amax_o_loc = 0.0f;
    #pragma unroll
    for (int i = 0; i < 8; i++) {
        const float il = 1.0f / l_run[i];
        amax_s_loc = fmaxf(amax_s_loc, il);          // row max prob = 1/l
        float4 o4;
        float r0 = oacc[i][0] * il * pv_scale;
        float r1 = oacc[i][1] * il * pv_scale;
        float r2 = oacc[i][2] * il * pv_scale;
        float r3 = oacc[i][3] * il * pv_scale;
        amax_o_loc = fmaxf(amax_o_loc, fmaxf(fmaxf(fabsf(r0), fabsf(r1)),
                                             fmaxf(fabsf(r2), fabsf(r3))));
        o4.x = r0 * o_scale; o4.y = r1 * o_scale;
        o4.z = r2 * o_scale; o4.w = r3 * o_scale;
        *(float4*)(out + base + (size_t)(q0 + ty * 8 + i) * HD + tx * 4) = o4;
    }

    // block amax reduction -> one atomic pair
    #pragma unroll
    for (int m = 16; m >= 1; m >>= 1) {
        amax_s_loc = fmaxf(amax_s_loc, __shfl_xor_sync(0xffffffffu, amax_s_loc, m));
        amax_o_loc = fmaxf(amax_o_loc, __shfl_xor_sync(0xffffffffu, amax_o_loc, m));
    }
    __syncthreads();               // Pt reusable as scratch
    const int wid = t >> 5;
    if ((t & 31) == 0) { Pt[wid] = amax_s_loc; Pt[8 + wid] = amax_o_loc; }
    __syncthreads();
    if (t == 0) {
        float as = Pt[0], ao = Pt[8];
        #pragma unroll
        for (int w = 1; w < 8; w++) { as = fmaxf(as, Pt[w]); ao = fmaxf(ao, Pt[8 + w]); }
        atomic_max_pos(&amax_tail[0], as);
        atomic_max_pos(&amax_tail[1], ao);
    }
}

extern "C" void kernel_launch(void* const* d_in, const int* in_sizes, int n_in,
                              void* d_out, int out_size) {
    const float* q   = (const float*)d_in[0];
    const float* k   = (const float*)d_in[1];
    const float* v   = (const float*)d_in[2];
    const float* dsq = (const float*)d_in[3];
    const float* dsk = (const float*)d_in[4];
    const float* dsv = (const float*)d_in[5];
    const float* qss = (const float*)d_in[6];
    const float* qso = (const float*)d_in[7];
    const float* dss = (const float*)d_in[8];
    float* out = (float*)d_out;

    float* tail = out + (out_size - 2);

    cudaFuncSetAttribute(flash_fwd_kernel,
                         cudaFuncAttributeMaxDynamicSharedMemorySize, SMEM_BYTES);

    init_amax_kernel<<<1, 1>>>(tail);

    dim3 grid(SEQ / BM, BH);                 // (16, 32)
    flash_fwd_kernel<<<grid, NTHR, SMEM_BYTES>>>(q, k, v, dsq, dsk, dsv, qss, qso, dss,
                                                 out, tail);
}

// round 4
// speedup vs baseline: 8.6923x; 2.5771x over previous
#include <cuda_runtime.h>
#include <cuda_bf16.h>
#include <cstdint>
#include <math.h>

#define BH   32
#define SEQ  2048
#define HD   64
#define BM   128
#define BN   64
#define NTHR 256

#define STRD   72                    // bf16 elems per smem row (64 + 8 pad) -> 144B rows
#define RB     (STRD * 2)            // row bytes
#define QHI_OFF  0
#define QLO_OFF  (QHI_OFF + BM * RB)
#define KHI_OFF  (QLO_OFF + BM * RB)
#define KLO_OFF  (KHI_OFF + BN * RB)
#define VTHI_OFF (KLO_OFF + BN * RB)
#define VTLO_OFF (VTHI_OFF + HD * RB)
#define RED_OFF  (VTLO_OFF + HD * RB)
#define SMEM_TOTAL (RED_OFF + 64 * 4)

__global__ void init_amax_kernel(float* tail) { tail[0] = 0.0f; tail[1] = 0.0f; }

__device__ __forceinline__ void atomic_max_pos(float* addr, float v) {
    atomicMax(reinterpret_cast<unsigned int*>(addr), __float_as_uint(v));
}
__device__ __forceinline__ uint32_t smem_u32(const void* p) {
    uint32_t a;
    asm("{ .reg .u64 t; cvta.to.shared.u64 t, %1; cvt.u32.u64 %0, t; }" : "=r"(a) : "l"(p));
    return a;
}
__device__ __forceinline__ void ldsm4(uint32_t r[4], uint32_t addr) {
    asm volatile("ldmatrix.sync.aligned.m8n8.x4.shared.b16 {%0,%1,%2,%3}, [%4];"
                 : "=r"(r[0]), "=r"(r[1]), "=r"(r[2]), "=r"(r[3]) : "r"(addr));
}
__device__ __forceinline__ void mma16816(float d[4], const uint32_t a[4],
                                         uint32_t b0, uint32_t b1) {
    asm volatile("mma.sync.aligned.m16n8k16.row.col.f32.bf16.bf16.f32 "
                 "{%0,%1,%2,%3},{%4,%5,%6,%7},{%8,%9},{%0,%1,%2,%3};"
                 : "+f"(d[0]), "+f"(d[1]), "+f"(d[2]), "+f"(d[3])
                 : "r"(a[0]), "r"(a[1]), "r"(a[2]), "r"(a[3]), "r"(b0), "r"(b1));
}
__device__ __forceinline__ uint32_t packbf(float lo, float hi) {
    __nv_bfloat162 h = __float22bfloat162_rn(make_float2(lo, hi));
    return *reinterpret_cast<uint32_t*>(&h);
}
__device__ __forceinline__ float2 unpackbf(uint32_t u) {
    return __bfloat1622float2(*reinterpret_cast<__nv_bfloat162*>(&u));
}

__global__ __launch_bounds__(NTHR) void fa_mma_kernel(
    const float* __restrict__ q, const float* __restrict__ k, const float* __restrict__ v,
    const float* __restrict__ dsq, const float* __restrict__ dsk, const float* __restrict__ dsv,
    const float* __restrict__ qss, const float* __restrict__ qso, const float* __restrict__ dss,
    float* __restrict__ out, float* __restrict__ amax_tail)
{
    extern __shared__ char smem[];
    const uint32_t sb = smem_u32(smem);
    float* redf = (float*)(smem + RED_OFF);

    const int t = threadIdx.x, w = t >> 5, lane = t & 31;
    const int g = lane >> 2, tig = lane & 3;
    const int subm = lane >> 3;
    // ldmatrix address components
    const int a_r = (lane & 7) + ((subm & 1) << 3);   // A: row offset
    const int a_c = ((subm >> 1) << 3);               // A: col offset
    const int b_r = (lane & 7) + ((subm >> 1) << 3);  // B: row offset
    const int b_c = ((subm & 1) << 3);                // B: col offset

    const int qt = (gridDim.x - 1) - blockIdx.x;      // heavy tiles first
    const int bh = blockIdx.y;
    const size_t base = (size_t)bh * SEQ * HD;
    const int q0 = qt * BM;

    const float qk_scale = dsq[0] * dsk[0] * 0.125f;
    const float pv_scale = qss[0] * dss[0] * dsv[0];
    const float o_scale  = qso[0];

    // ---- load Q once: scale, bf16 hi/lo split, row-major ----
    for (int i = t; i < BM * (HD / 4); i += NTHR) {
        int r = i >> 4, c = (i & 15) * 4;
        float4 val = *(const float4*)(q + base + (size_t)(q0 + r) * HD + c);
        val.x *= qk_scale; val.y *= qk_scale; val.z *= qk_scale; val.w *= qk_scale;
        uint32_t h01 = packbf(val.x, val.y), h23 = packbf(val.z, val.w);
        float2 f01 = unpackbf(h01), f23 = unpackbf(h23);
        uint32_t l01 = packbf(val.x - f01.x, val.y - f01.y);
        uint32_t l23 = packbf(val.z - f23.x, val.w - f23.y);
        *(uint2*)(smem + QHI_OFF + r * RB + c * 2) = make_uint2(h01, h23);
        *(uint2*)(smem + QLO_OFF + r * RB + c * 2) = make_uint2(l01, l23);
    }

    float o_acc[8][4];
    #pragma unroll
    for (int nb = 0; nb < 8; nb++)
        #pragma unroll
        for (int j = 0; j < 4; j++) o_acc[nb][j] = 0.0f;
    float m0 = -1e30f, m1 = -1e30f, l0 = 0.0f, l1 = 0.0f;

    const int row_hi = q0 + w * 16 + 15;              // max row this warp owns
    const int n_tiles = 2 * qt + 2;

    for (int kt = 0; kt < n_tiles; kt++) {
        const int n0 = kt * BN;
        __syncthreads();                              // prev-tile reads done

        // ---- load K (row-major) + V^T, hi/lo split ----
        for (int i = t; i < BN * (HD / 4); i += NTHR) {
            int r = i >> 4, c = (i & 15) * 4;
            float4 kk = *(const float4*)(k + base + (size_t)(n0 + r) * HD + c);
            uint32_t h01 = packbf(kk.x, kk.y), h23 = packbf(kk.z, kk.w);
            float2 f01 = unpackbf(h01), f23 = unpackbf(h23);
            uint32_t l01 = packbf(kk.x - f01.x, kk.y - f01.y);
            uint32_t l23 = packbf(kk.z - f23.x, kk.w - f23.y);
            *(uint2*)(smem + KHI_OFF + r * RB + c * 2) = make_uint2(h01, h23);
            *(uint2*)(smem + KLO_OFF + r * RB + c * 2) = make_uint2(l01, l23);

            float4 vv = *(const float4*)(v + base + (size_t)(n0 + r) * HD + c);
            float ve[4] = {vv.x, vv.y, vv.z, vv.w};
            #pragma unroll
            for (int j = 0; j < 4; j++) {
                __nv_bfloat16 hb = __float2bfloat16(ve[j]);
                float lof = ve[j] - __bfloat162float(hb);
                __nv_bfloat16 lb = __float2bfloat16(lof);
                *(__nv_bfloat16*)(smem + VTHI_OFF + (c + j) * RB + r * 2) = hb;
                *(__nv_bfloat16*)(smem + VTLO_OFF + (c + j) * RB + r * 2) = lb;
            }
        }
        __syncthreads();

        const bool active = (n0 <= row_hi);
        if (active) {
            // ---- S = Q K^T : 3-pass bf16 ----
            float s[8][4];
            #pragma unroll
            for (int nb = 0; nb < 8; nb++)
                #pragma unroll
                for (int j = 0; j < 4; j++) s[nb][j] = 0.0f;

            #pragma unroll
            for (int kb = 0; kb < 4; kb++) {
                uint32_t ah[4], al[4], b[4];
                uint32_t abase = sb + (uint32_t)((w * 16 + a_r) * RB + (kb * 16 + a_c) * 2);
                ldsm4(ah, abase + QHI_OFF);
                ldsm4(al, abase + QLO_OFF);
                #pragma unroll
                for (int np = 0; np < 4; np++) {
                    uint32_t bbase = sb + (uint32_t)((np * 16 + b_r) * RB + (kb * 16 + b_c) * 2);
                    ldsm4(b, bbase + KHI_OFF);
                    mma16816(s[2 * np],     ah, b[0], b[1]);
                    mma16816(s[2 * np + 1], ah, b[2], b[3]);
                    mma16816(s[2 * np],     al, b[0], b[1]);
                    mma16816(s[2 * np + 1], al, b[2], b[3]);
                    ldsm4(b, bbase + KLO_OFF);
                    mma16816(s[2 * np],     ah, b[0], b[1]);
                    mma16816(s[2 * np + 1], ah, b[2], b[3]);
                }
            }

            // ---- causal mask ----
            if (n0 + BN - 1 > q0 + w * 16) {
                const int r0g = q0 + w * 16 + g, r1g = r0g + 8;
                #pragma unroll
                for (int nb = 0; nb < 8; nb++) {
                    const int c0 = n0 + nb * 8 + tig * 2;
                    if (c0 > r0g)     s[nb][0] = -1e30f;
                    if (c0 + 1 > r0g) s[nb][1] = -1e30f;
                    if (c0 > r1g)     s[nb][2] = -1e30f;
                    if (c0 + 1 > r1g) s[nb][3] = -1e30f;
                }
            }

            // ---- online softmax (2 rows/thread, quad shfl) ----
            float mx0 = -1e30f, mx1 = -1e30f;
            #pragma unroll
            for (int nb = 0; nb < 8; nb++) {
                mx0 = fmaxf(mx0, fmaxf(s[nb][0], s[nb][1]));
                mx1 = fmaxf(mx1, fmaxf(s[nb][2], s[nb][3]));
            }
            mx0 = fmaxf(mx0, __shfl_xor_sync(0xffffffffu, mx0, 1));
            mx0 = fmaxf(mx0, __shfl_xor_sync(0xffffffffu, mx0, 2));
            mx1 = fmaxf(mx1, __shfl_xor_sync(0xffffffffu, mx1, 1));
            mx1 = fmaxf(mx1, __shfl_xor_sync(0xffffffffu, mx1, 2));
            const float mn0 = fmaxf(m0, mx0), mn1 = fmaxf(m1, mx1);
            const float al0 = __expf(m0 - mn0), al1 = __expf(m1 - mn1);
            float sum0 = 0.0f, sum1 = 0.0f;
            #pragma unroll
            for (int nb = 0; nb < 8; nb++) {
                s[nb][0] = __expf(s[nb][0] - mn0); sum0 += s[nb][0];
                s[nb][1] = __expf(s[nb][1] - mn0); sum0 += s[nb][1];
                s[nb][2] = __expf(s[nb][2] - mn1); sum1 += s[nb][2];
                s[nb][3] = __expf(s[nb][3] - mn1); sum1 += s[nb][3];
            }
            sum0 += __shfl_xor_sync(0xffffffffu, sum0, 1);
            sum0 += __shfl_xor_sync(0xffffffffu, sum0, 2);
            sum1 += __shfl_xor_sync(0xffffffffu, sum1, 1);
            sum1 += __shfl_xor_sync(0xffffffffu, sum1, 2);
            l0 = l0 * al0 + sum0; l1 = l1 * al1 + sum1;
            m0 = mn0; m1 = mn1;
            #pragma unroll
            for (int nb = 0; nb < 8; nb++) {
                o_acc[nb][0] *= al0; o_acc[nb][1] *= al0;
                o_acc[nb][2] *= al1; o_acc[nb][3] *= al1;
            }

            // ---- O += P V : P fragments built in-register, 3-pass ----
            #pragma unroll
            for (int kb = 0; kb < 4; kb++) {
                uint32_t ah[4], al_[4], b[4];
                ah[0] = packbf(s[2 * kb][0], s[2 * kb][1]);
                ah[1] = packbf(s[2 * kb][2], s[2 * kb][3]);
                ah[2] = packbf(s[2 * kb + 1][0], s[2 * kb + 1][1]);
                ah[3] = packbf(s[2 * kb + 1][2], s[2 * kb + 1][3]);
                float2 u0 = unpackbf(ah[0]), u1 = unpackbf(ah[1]);
                float2 u2 = unpackbf(ah[2]), u3 = unpackbf(ah[3]);
                al_[0] = packbf(s[2 * kb][0] - u0.x, s[2 * kb][1] - u0.y);
                al_[1] = packbf(s[2 * kb][2] - u1.x, s[2 * kb][3] - u1.y);
                al_[2] = packbf(s[2 * kb + 1][0] - u2.x, s[2 * kb + 1][1] - u2.y);
                al_[3] = packbf(s[2 * kb + 1][2] - u3.x, s[2 * kb + 1][3] - u3.y);
                #pragma unroll
                for (int np = 0; np < 4; np++) {
                    uint32_t bbase = sb + (uint32_t)((np * 16 + b_r) * RB + (kb * 16 + b_c) * 2);
                    ldsm4(b, bbase + VTHI_OFF);
                    mma16816(o_acc[2 * np],     ah, b[0], b[1]);
                    mma16816(o_acc[2 * np + 1], ah, b[2], b[3]);
                    mma16816(o_acc[2 * np],     al_, b[0], b[1]);
                    mma16816(o_acc[2 * np + 1], al_, b[2], b[3]);
                    ldsm4(b, bbase + VTLO_OFF);
                    mma16816(o_acc[2 * np],     ah, b[0], b[1]);
                    mma16816(o_acc[2 * np + 1], ah, b[2], b[3]);
                }
            }
        }
    }

    // ---- epilogue: normalize, scales, amax, store ----
    const float il0 = 1.0f / l0, il1 = 1.0f / l1;
    float amax_s_loc = fmaxf(il0, il1);
    float amax_o_loc = 0.0f;
    const int r0g = q0 + w * 16 + g, r1g = r0g + 8;
    #pragma unroll
    for (int nb = 0; nb < 8; nb++) {
        float v0 = o_acc[nb][0] * il0 * pv_scale;
        float v1 = o_acc[nb][1] * il0 * pv_scale;
        float v2 = o_acc[nb][2] * il1 * pv_scale;
        float v3 = o_acc[nb][3] * il1 * pv_scale;
        amax_o_loc = fmaxf(amax_o_loc, fmaxf(fmaxf(fabsf(v0), fabsf(v1)),
                                             fmaxf(fabsf(v2), fabsf(v3))));
        const int c = nb * 8 + tig * 2;
        *(float2*)(out + base + (size_t)r0g * HD + c) = make_float2(v0 * o_scale, v1 * o_scale);
        *(float2*)(out + base + (size_t)r1g * HD + c) = make_float2(v2 * o_scale, v3 * o_scale);
    }

    #pragma unroll
    for (int msk = 16; msk >= 1; msk >>= 1) {
        amax_s_loc = fmaxf(amax_s_loc, __shfl_xor_sync(0xffffffffu, amax_s_loc, msk));
        amax_o_loc = fmaxf(amax_o_loc, __shfl_xor_sync(0xffffffffu, amax_o_loc, msk));
    }
    if (lane == 0) { redf[w] = amax_s_loc; redf[8 + w] = amax_o_loc; }
    __syncthreads();
    if (t == 0) {
        float as = redf[0], ao = redf[8];
        #pragma unroll
        for (int i = 1; i < 8; i++) { as = fmaxf(as, redf[i]); ao = fmaxf(ao, redf[8 + i]); }
        atomic_max_pos(&amax_tail[0], as);
        atomic_max_pos(&amax_tail[1], ao);
    }
}

extern "C" void kernel_launch(void* const* d_in, const int* in_sizes, int n_in,
                              void* d_out, int out_size) {
    const float* q   = (const float*)d_in[0];
    const float* k   = (const float*)d_in[1];
    const float* v   = (const float*)d_in[2];
    const float* dsq = (const float*)d_in[3];
    const float* dsk = (const float*)d_in[4];
    const float* dsv = (const float*)d_in[5];
    const float* qss = (const float*)d_in[6];
    const float* qso = (const float*)d_in[7];
    const float* dss = (const float*)d_in[8];
    float* out = (float*)d_out;
    float* tail = out + (out_size - 2);

    cudaFuncSetAttribute(fa_mma_kernel,
                         cudaFuncAttributeMaxDynamicSharedMemorySize, SMEM_TOTAL);

    init_amax_kernel<<<1, 1>>>(tail);

    dim3 grid(SEQ / BM, BH);                 // (16, 32)
    fa_mma_kernel<<<grid, NTHR, SMEM_TOTAL>>>(q, k, v, dsq, dsk, dsv, qss, qso, dss,
                                              out, tail);
}

// round 5
// speedup vs baseline: 11.9391x; 1.3735x over previous
#include <cuda_runtime.h>
#include <cuda_bf16.h>
#include <cstdint>
#include <math.h>

#define BH   32
#define SEQ  2048
#define HD   64
#define BM   128
#define BN   64
#define NTHR 256
#define LOG2E 1.4426950408889634f

#define STRD 72
#define RB   144                       // smem row bytes (128 data + 16 pad)
#define QHI_OFF 0
#define QLO_OFF 18432
#define STG_OFF 36864                  // two 36864B stages follow
#define STG_SZ  36864
// within a stage: KHI +0, KLO +9216, VTHI +18432, VTLO +27648
#define RED_OFF (STG_OFF + 2 * STG_SZ) // 110592
#define SMEM_TOTAL (RED_OFF + 256)

// pre-converted operands (written by prep_kernel each launch)
__device__ __nv_bfloat16 g_khi[(size_t)BH * SEQ * HD];
__device__ __nv_bfloat16 g_klo[(size_t)BH * SEQ * HD];
__device__ __nv_bfloat16 g_vthi[(size_t)BH * HD * SEQ];   // [bh][d][n]
__device__ __nv_bfloat16 g_vtlo[(size_t)BH * HD * SEQ];

__global__ void init_amax_kernel(float* tail) { tail[0] = 0.0f; tail[1] = 0.0f; }

__device__ __forceinline__ void atomic_max_pos(float* addr, float v) {
    atomicMax(reinterpret_cast<unsigned int*>(addr), __float_as_uint(v));
}
__device__ __forceinline__ uint32_t smem_u32(const void* p) {
    uint32_t a;
    asm("{ .reg .u64 t; cvta.to.shared.u64 t, %1; cvt.u32.u64 %0, t; }" : "=r"(a) : "l"(p));
    return a;
}
__device__ __forceinline__ void ldsm4(uint32_t r[4], uint32_t addr) {
    asm volatile("ldmatrix.sync.aligned.m8n8.x4.shared.b16 {%0,%1,%2,%3}, [%4];"
                 : "=r"(r[0]), "=r"(r[1]), "=r"(r[2]), "=r"(r[3]) : "r"(addr));
}
__device__ __forceinline__ void mma16816(float d[4], const uint32_t a[4],
                                         uint32_t b0, uint32_t b1) {
    asm volatile("mma.sync.aligned.m16n8k16.row.col.f32.bf16.bf16.f32 "
                 "{%0,%1,%2,%3},{%4,%5,%6,%7},{%8,%9},{%0,%1,%2,%3};"
                 : "+f"(d[0]), "+f"(d[1]), "+f"(d[2]), "+f"(d[3])
                 : "r"(a[0]), "r"(a[1]), "r"(a[2]), "r"(a[3]), "r"(b0), "r"(b1));
}
__device__ __forceinline__ uint32_t packbf(float lo, float hi) {
    __nv_bfloat162 h = __float22bfloat162_rn(make_float2(lo, hi));
    return *reinterpret_cast<uint32_t*>(&h);
}
__device__ __forceinline__ float2 unpackbf(uint32_t u) {
    return __bfloat1622float2(*reinterpret_cast<__nv_bfloat162*>(&u));
}
__device__ __forceinline__ float ex2(float x) {
    float r; asm("ex2.approx.f32 %0, %1;" : "=f"(r) : "f"(x)); return r;
}
__device__ __forceinline__ void cpasync16(uint32_t dst, const void* src) {
    asm volatile("cp.async.cg.shared.global [%0], [%1], 16;" :: "r"(dst), "l"(src) : "memory");
}
#define CP_COMMIT() asm volatile("cp.async.commit_group;" ::: "memory")
#define CP_WAIT0()  asm volatile("cp.async.wait_group 0;" ::: "memory")

// ---- pre-pass: K -> bf16 hi/lo, V -> V^T bf16 hi/lo ----
__global__ __launch_bounds__(256) void prep_kernel(const float* __restrict__ k,
                                                   const float* __restrict__ v) {
    __shared__ float vs[64][65];
    const int n0 = blockIdx.x * 64;
    const int bh = blockIdx.y;
    const int t = threadIdx.x;
    const size_t base = (size_t)bh * SEQ * HD;

    for (int i = t; i < 64 * 16; i += 256) {
        int r = i >> 4, c = (i & 15) * 4;
        size_t eo = base + (size_t)(n0 + r) * HD + c;
        float4 kk = *(const float4*)(k + eo);
        uint32_t h01 = packbf(kk.x, kk.y), h23 = packbf(kk.z, kk.w);
        float2 f01 = unpackbf(h01), f23 = unpackbf(h23);
        uint32_t l01 = packbf(kk.x - f01.x, kk.y - f01.y);
        uint32_t l23 = packbf(kk.z - f23.x, kk.w - f23.y);
        *(uint2*)((uint16_t*)g_khi + eo) = make_uint2(h01, h23);
        *(uint2*)((uint16_t*)g_klo + eo) = make_uint2(l01, l23);
        float4 vv = *(const float4*)(v + eo);
        vs[r][c] = vv.x; vs[r][c + 1] = vv.y; vs[r][c + 2] = vv.z; vs[r][c + 3] = vv.w;
    }
    __syncthreads();
    const int d = t >> 2;
    const int nn0 = (t & 3) * 16;
    const size_t vbase = ((size_t)bh * HD + d) * SEQ + n0;
    #pragma unroll
    for (int nb = 0; nb < 4; nb++) {
        int n = nn0 + nb * 4;
        float a0 = vs[n][d], a1 = vs[n + 1][d], a2 = vs[n + 2][d], a3 = vs[n + 3][d];
        uint32_t h01 = packbf(a0, a1), h23 = packbf(a2, a3);
        float2 f01 = unpackbf(h01), f23 = unpackbf(h23);
        uint32_t l01 = packbf(a0 - f01.x, a1 - f01.y);
        uint32_t l23 = packbf(a2 - f23.x, a3 - f23.y);
        *(uint2*)((uint16_t*)g_vthi + vbase + n) = make_uint2(h01, h23);
        *(uint2*)((uint16_t*)g_vtlo + vbase + n) = make_uint2(l01, l23);
    }
}

// async-load one 64-row K/V tile (bf16 hi/lo, pre-converted) into a smem stage
__device__ __forceinline__ void issue_tile(uint32_t stg, int bh, int n0, int t) {
    const char* skhi = (const char*)g_khi + ((size_t)bh * SEQ + n0) * HD * 2;
    const char* sklo = (const char*)g_klo + ((size_t)bh * SEQ + n0) * HD * 2;
    const char* svhi = (const char*)g_vthi + ((size_t)bh * HD * SEQ + n0) * 2;
    const char* svlo = (const char*)g_vtlo + ((size_t)bh * HD * SEQ + n0) * 2;
    #pragma unroll
    for (int j = 0; j < 2; j++) {
        int rid = (j << 8) + t;            // 0..511 chunks per region
        int r = rid >> 3, c16 = rid & 7;
        uint32_t dk = stg + r * RB + c16 * 16;
        cpasync16(dk,         skhi + rid * 16);            // K rows contiguous 128B
        cpasync16(dk + 9216,  sklo + rid * 16);
        uint32_t dv = stg + 18432 + r * RB + c16 * 16;
        size_t vsrc = (size_t)r * (SEQ * 2) + c16 * 16;    // V^T rows stride 4096B
        cpasync16(dv,         svhi + vsrc);
        cpasync16(dv + 9216,  svlo + vsrc);
    }
}

__global__ __launch_bounds__(NTHR, 2) void fa_mma_kernel(
    const float* __restrict__ q,
    const float* __restrict__ dsq, const float* __restrict__ dsk, const float* __restrict__ dsv,
    const float* __restrict__ qss, const float* __restrict__ qso, const float* __restrict__ dss,
    float* __restrict__ out, float* __restrict__ amax_tail)
{
    extern __shared__ char smem[];
    const uint32_t sb = smem_u32(smem);
    float* redf = (float*)(smem + RED_OFF);

    const int t = threadIdx.x, w = t >> 5, lane = t & 31;
    const int g = lane >> 2, tig = lane & 3;
    const int subm = lane >> 3;
    const int a_r = (lane & 7) + ((subm & 1) << 3);
    const int a_c = ((subm >> 1) << 3);
    const int b_r = (lane & 7) + ((subm >> 1) << 3);
    const int b_c = ((subm & 1) << 3);

    const int qt = (gridDim.x - 1) - blockIdx.x;          // heavy tiles first
    const int bh = blockIdx.y;
    const size_t base = (size_t)bh * SEQ * HD;
    const int q0 = qt * BM;

    const float qk_scale = dsq[0] * dsk[0] * 0.125f * LOG2E;   // ex2 domain
    const float pv_scale = qss[0] * dss[0] * dsv[0];
    const float o_scale  = qso[0];

    // prefetch tile 0 first, then convert Q
    issue_tile(sb + STG_OFF, bh, 0, t);
    CP_COMMIT();

    for (int i = t; i < BM * (HD / 4); i += NTHR) {
        int r = i >> 4, c = (i & 15) * 4;
        float4 val = *(const float4*)(q + base + (size_t)(q0 + r) * HD + c);
        val.x *= qk_scale; val.y *= qk_scale; val.z *= qk_scale; val.w *= qk_scale;
        uint32_t h01 = packbf(val.x, val.y), h23 = packbf(val.z, val.w);
        float2 f01 = unpackbf(h01), f23 = unpackbf(h23);
        uint32_t l01 = packbf(val.x - f01.x, val.y - f01.y);
        uint32_t l23 = packbf(val.z - f23.x, val.w - f23.y);
        *(uint2*)(smem + QHI_OFF + r * RB + c * 2) = make_uint2(h01, h23);
        *(uint2*)(smem + QLO_OFF + r * RB + c * 2) = make_uint2(l01, l23);
    }

    float o_acc[8][4];
    #pragma unroll
    for (int nb = 0; nb < 8; nb++)
        #pragma unroll
        for (int j = 0; j < 4; j++) o_acc[nb][j] = 0.0f;
    float m0 = -1e30f, m1 = -1e30f, l0 = 0.0f, l1 = 0.0f;

    const int row_hi = q0 + w * 16 + 15;
    const int n_tiles = 2 * qt + 2;

    for (int kt = 0; kt < n_tiles; kt++) {
        const int n0 = kt * BN;
        CP_WAIT0();                      // stage (kt&1) ready
        __syncthreads();                 // data visible; prev compute done
        if (kt + 1 < n_tiles) {
            issue_tile(sb + STG_OFF + ((kt + 1) & 1) * STG_SZ, bh, n0 + BN, t);
            CP_COMMIT();
        }
        const uint32_t stg = sb + STG_OFF + (kt & 1) * STG_SZ;

        const bool active = (n0 <= row_hi);
        if (active) {
            // ---- S = Q K^T : 3-pass bf16 ----
            float s[8][4];
            #pragma unroll
            for (int nb = 0; nb < 8; nb++)
                #pragma unroll
                for (int j = 0; j < 4; j++) s[nb][j] = 0.0f;

            #pragma unroll
            for (int kb = 0; kb < 4; kb++) {
                uint32_t ah[4], al[4], b[4];
                uint32_t abase = sb + (uint32_t)((w * 16 + a_r) * RB + (kb * 16 + a_c) * 2);
                ldsm4(ah, abase + QHI_OFF);
                ldsm4(al, abase + QLO_OFF);
                #pragma unroll
                for (int np = 0; np < 4; np++) {
                    uint32_t bbase = stg + (uint32_t)((np * 16 + b_r) * RB + (kb * 16 + b_c) * 2);
                    ldsm4(b, bbase);                    // KHI
                    mma16816(s[2 * np],     ah, b[0], b[1]);
                    mma16816(s[2 * np + 1], ah, b[2], b[3]);
                    mma16816(s[2 * np],     al, b[0], b[1]);
                    mma16816(s[2 * np + 1], al, b[2], b[3]);
                    ldsm4(b, bbase + 9216);             // KLO
                    mma16816(s[2 * np],     ah, b[0], b[1]);
                    mma16816(s[2 * np + 1], ah, b[2], b[3]);
                }
            }

            // ---- causal mask ----
            if (n0 + BN - 1 > q0 + w * 16) {
                const int r0g = q0 + w * 16 + g, r1g = r0g + 8;
                #pragma unroll
                for (int nb = 0; nb < 8; nb++) {
                    const int c0 = n0 + nb * 8 + tig * 2;
                    if (c0 > r0g)     s[nb][0] = -1e30f;
                    if (c0 + 1 > r0g) s[nb][1] = -1e30f;
                    if (c0 > r1g)     s[nb][2] = -1e30f;
                    if (c0 + 1 > r1g) s[nb][3] = -1e30f;
                }
            }

            // ---- online softmax (base-2 domain) ----
            float mx0 = -1e30f, mx1 = -1e30f;
            #pragma unroll
            for (int nb = 0; nb < 8; nb++) {
                mx0 = fmaxf(mx0, fmaxf(s[nb][0], s[nb][1]));
                mx1 = fmaxf(mx1, fmaxf(s[nb][2], s[nb][3]));
            }
            mx0 = fmaxf(mx0, __shfl_xor_sync(0xffffffffu, mx0, 1));
            mx0 = fmaxf(mx0, __shfl_xor_sync(0xffffffffu, mx0, 2));
            mx1 = fmaxf(mx1, __shfl_xor_sync(0xffffffffu, mx1, 1));
            mx1 = fmaxf(mx1, __shfl_xor_sync(0xffffffffu, mx1, 2));
            const float mn0 = fmaxf(m0, mx0), mn1 = fmaxf(m1, mx1);
            const float al0 = ex2(m0 - mn0), al1 = ex2(m1 - mn1);
            float sum0 = 0.0f, sum1 = 0.0f;
            #pragma unroll
            for (int nb = 0; nb < 8; nb++) {
                s[nb][0] = ex2(s[nb][0] - mn0); sum0 += s[nb][0];
                s[nb][1] = ex2(s[nb][1] - mn0); sum0 += s[nb][1];
                s[nb][2] = ex2(s[nb][2] - mn1); sum1 += s[nb][2];
                s[nb][3] = ex2(s[nb][3] - mn1); sum1 += s[nb][3];
            }
            sum0 += __shfl_xor_sync(0xffffffffu, sum0, 1);
            sum0 += __shfl_xor_sync(0xffffffffu, sum0, 2);
            sum1 += __shfl_xor_sync(0xffffffffu, sum1, 1);
            sum1 += __shfl_xor_sync(0xffffffffu, sum1, 2);
            l0 = l0 * al0 + sum0; l1 = l1 * al1 + sum1;
            m0 = mn0; m1 = mn1;
            #pragma unroll
            for (int nb = 0; nb < 8; nb++) {
                o_acc[nb][0] *= al0; o_acc[nb][1] *= al0;
                o_acc[nb][2] *= al1; o_acc[nb][3] *= al1;
            }

            // ---- O += P V : P fragments in-register, 3-pass ----
            #pragma unroll
            for (int kb = 0; kb < 4; kb++) {
                uint32_t ah[4], al_[4], b[4];
                ah[0] = packbf(s[2 * kb][0], s[2 * kb][1]);
                ah[1] = packbf(s[2 * kb][2], s[2 * kb][3]);
                ah[2] = packbf(s[2 * kb + 1][0], s[2 * kb + 1][1]);
                ah[3] = packbf(s[2 * kb + 1][2], s[2 * kb + 1][3]);
                float2 u0 = unpackbf(ah[0]), u1 = unpackbf(ah[1]);
                float2 u2 = unpackbf(ah[2]), u3 = unpackbf(ah[3]);
                al_[0] = packbf(s[2 * kb][0] - u0.x, s[2 * kb][1] - u0.y);
                al_[1] = packbf(s[2 * kb][2] - u1.x, s[2 * kb][3] - u1.y);
                al_[2] = packbf(s[2 * kb + 1][0] - u2.x, s[2 * kb + 1][1] - u2.y);
                al_[3] = packbf(s[2 * kb + 1][2] - u3.x, s[2 * kb + 1][3] - u3.y);
                #pragma unroll
                for (int np = 0; np < 4; np++) {
                    uint32_t bbase = stg + 18432 +
                        (uint32_t)((np * 16 + b_r) * RB + (kb * 16 + b_c) * 2);
                    ldsm4(b, bbase);                    // VTHI
                    mma16816(o_acc[2 * np],     ah, b[0], b[1]);
                    mma16816(o_acc[2 * np + 1], ah, b[2], b[3]);
                    mma16816(o_acc[2 * np],     al_, b[0], b[1]);
                    mma16816(o_acc[2 * np + 1], al_, b[2], b[3]);
                    ldsm4(b, bbase + 9216);             // VTLO
                    mma16816(o_acc[2 * np],     ah, b[0], b[1]);
                    mma16816(o_acc[2 * np + 1], ah, b[2], b[3]);
                }
            }
        }
    }

    // ---- epilogue ----
    const float il0 = 1.0f / l0, il1 = 1.0f / l1;
    float amax_s_loc = fmaxf(il0, il1);
    float amax_o_loc = 0.0f;
    const int r0g = q0 + w * 16 + g, r1g = r0g + 8;
    #pragma unroll
    for (int nb = 0; nb < 8; nb++) {
        float v0 = o_acc[nb][0] * il0 * pv_scale;
        float v1 = o_acc[nb][1] * il0 * pv_scale;
        float v2 = o_acc[nb][2] * il1 * pv_scale;
        float v3 = o_acc[nb][3] * il1 * pv_scale;
        amax_o_loc = fmaxf(amax_o_loc, fmaxf(fmaxf(fabsf(v0), fabsf(v1)),
                                             fmaxf(fabsf(v2), fabsf(v3))));
        const int c = nb * 8 + tig * 2;
        *(float2*)(out + base + (size_t)r0g * HD + c) = make_float2(v0 * o_scale, v1 * o_scale);
        *(float2*)(out + base + (size_t)r1g * HD + c) = make_float2(v2 * o_scale, v3 * o_scale);
    }

    #pragma unroll
    for (int msk = 16; msk >= 1; msk >>= 1) {
        amax_s_loc = fmaxf(amax_s_loc, __shfl_xor_sync(0xffffffffu, amax_s_loc, msk));
        amax_o_loc = fmaxf(amax_o_loc, __shfl_xor_sync(0xffffffffu, amax_o_loc, msk));
    }
    if (lane == 0) { redf[w] = amax_s_loc; redf[8 + w] = amax_o_loc; }
    __syncthreads();
    if (t == 0) {
        float as = redf[0], ao = redf[8];
        #pragma unroll
        for (int i = 1; i < 8; i++) { as = fmaxf(as, redf[i]); ao = fmaxf(ao, redf[8 + i]); }
        atomic_max_pos(&amax_tail[0], as);
        atomic_max_pos(&amax_tail[1], ao);
    }
}

extern "C" void kernel_launch(void* const* d_in, const int* in_sizes, int n_in,
                              void* d_out, int out_size) {
    const float* q   = (const float*)d_in[0];
    const float* k   = (const float*)d_in[1];
    const float* v   = (const float*)d_in[2];
    const float* dsq = (const float*)d_in[3];
    const float* dsk = (const float*)d_in[4];
    const float* dsv = (const float*)d_in[5];
    const float* qss = (const float*)d_in[6];
    const float* qso = (const float*)d_in[7];
    const float* dss = (const float*)d_in[8];
    float* out = (float*)d_out;
    float* tail = out + (out_size - 2);

    cudaFuncSetAttribute(fa_mma_kernel,
                         cudaFuncAttributeMaxDynamicSharedMemorySize, SMEM_TOTAL);

    init_amax_kernel<<<1, 1>>>(tail);
    prep_kernel<<<dim3(SEQ / 64, BH), 256>>>(k, v);

    dim3 grid(SEQ / BM, BH);                 // (16, 32)
    fa_mma_kernel<<<grid, NTHR, SMEM_TOTAL>>>(q, dsq, dsk, dsv, qss, qso, dss,
                                              out, tail);
}

// round 6
// speedup vs baseline: 17.4661x; 1.4629x over previous
#include <cuda_runtime.h>
#include <cuda_fp16.h>
#include <cstdint>
#include <math.h>

#define BH   32
#define SEQ  2048
#define HD   64
#define BM   128
#define BN   64
#define NTHR 256
#define LOG2E 1.4426950408889634f

#define RB   144                       // smem row bytes (128 data + 16 pad)
#define QHI_OFF 0
#define QLO_OFF 18432
#define STG_OFF 36864                  // two 18432B stages follow
#define STG_SZ  18432
// within a stage: KHI +0, VTHI +9216
#define RED_OFF (STG_OFF + 2 * STG_SZ) // 73728
#define SMEM_TOTAL (RED_OFF + 256)

// pre-converted operands (written by prep_kernel each launch)
__device__ __half g_khi[(size_t)BH * SEQ * HD];
__device__ __half g_vthi[(size_t)BH * HD * SEQ];   // [bh][d][n]

__global__ void init_amax_kernel(float* tail) { tail[0] = 0.0f; tail[1] = 0.0f; }

__device__ __forceinline__ void atomic_max_pos(float* addr, float v) {
    atomicMax(reinterpret_cast<unsigned int*>(addr), __float_as_uint(v));
}
__device__ __forceinline__ uint32_t smem_u32(const void* p) {
    uint32_t a;
    asm("{ .reg .u64 t; cvta.to.shared.u64 t, %1; cvt.u32.u64 %0, t; }" : "=r"(a) : "l"(p));
    return a;
}
__device__ __forceinline__ void ldsm4(uint32_t r[4], uint32_t addr) {
    asm volatile("ldmatrix.sync.aligned.m8n8.x4.shared.b16 {%0,%1,%2,%3}, [%4];"
                 : "=r"(r[0]), "=r"(r[1]), "=r"(r[2]), "=r"(r[3]) : "r"(addr));
}
__device__ __forceinline__ void mma16816(float d[4], const uint32_t a[4],
                                         uint32_t b0, uint32_t b1) {
    asm volatile("mma.sync.aligned.m16n8k16.row.col.f32.f16.f16.f32 "
                 "{%0,%1,%2,%3},{%4,%5,%6,%7},{%8,%9},{%0,%1,%2,%3};"
                 : "+f"(d[0]), "+f"(d[1]), "+f"(d[2]), "+f"(d[3])
                 : "r"(a[0]), "r"(a[1]), "r"(a[2]), "r"(a[3]), "r"(b0), "r"(b1));
}
__device__ __forceinline__ uint32_t packhf(float x, float y) {
    __half2 h = __float22half2_rn(make_float2(x, y));
    return *reinterpret_cast<uint32_t*>(&h);
}
__device__ __forceinline__ float2 unpackhf(uint32_t u) {
    return __half22float2(*reinterpret_cast<__half2*>(&u));
}
__device__ __forceinline__ float ex2(float x) {
    float r; asm("ex2.approx.f32 %0, %1;" : "=f"(r) : "f"(x)); return r;
}
__device__ __forceinline__ void cpasync16(uint32_t dst, const void* src) {
    asm volatile("cp.async.cg.shared.global [%0], [%1], 16;" :: "r"(dst), "l"(src) : "memory");
}
#define CP_COMMIT() asm volatile("cp.async.commit_group;" ::: "memory")
#define CP_WAIT0()  asm volatile("cp.async.wait_group 0;" ::: "memory")

// ---- pre-pass: K -> fp16, V -> V^T fp16 ----
__global__ __launch_bounds__(256) void prep_kernel(const float* __restrict__ k,
                                                   const float* __restrict__ v) {
    __shared__ float vs[64][65];
    const int n0 = blockIdx.x * 64;
    const int bh = blockIdx.y;
    const int t = threadIdx.x;
    const size_t base = (size_t)bh * SEQ * HD;

    for (int i = t; i < 64 * 16; i += 256) {
        int r = i >> 4, c = (i & 15) * 4;
        size_t eo = base + (size_t)(n0 + r) * HD + c;
        float4 kk = *(const float4*)(k + eo);
        *(uint2*)((uint16_t*)g_khi + eo) =
            make_uint2(packhf(kk.x, kk.y), packhf(kk.z, kk.w));
        float4 vv = *(const float4*)(v + eo);
        vs[r][c] = vv.x; vs[r][c + 1] = vv.y; vs[r][c + 2] = vv.z; vs[r][c + 3] = vv.w;
    }
    __syncthreads();
    const int d = t >> 2;
    const int nn0 = (t & 3) * 16;
    const size_t vbase = ((size_t)bh * HD + d) * SEQ + n0;
    #pragma unroll
    for (int nb = 0; nb < 4; nb++) {
        int n = nn0 + nb * 4;
        *(uint2*)((uint16_t*)g_vthi + vbase + n) =
            make_uint2(packhf(vs[n][d], vs[n + 1][d]), packhf(vs[n + 2][d], vs[n + 3][d]));
    }
}

// async-load one 64-row K/V^T tile (fp16, pre-converted) into a smem stage
__device__ __forceinline__ void issue_tile(uint32_t stg, int bh, int n0, int t) {
    const char* skhi = (const char*)g_khi + ((size_t)bh * SEQ + n0) * HD * 2;
    const char* svhi = (const char*)g_vthi + ((size_t)bh * HD * SEQ + n0) * 2;
    #pragma unroll
    for (int j = 0; j < 2; j++) {
        int rid = (j << 8) + t;            // 0..511 chunks per region
        int r = rid >> 3, c16 = rid & 7;
        cpasync16(stg + r * RB + c16 * 16, skhi + rid * 16);               // K rows 128B
        cpasync16(stg + 9216 + r * RB + c16 * 16,
                  svhi + (size_t)r * (SEQ * 2) + c16 * 16);                // V^T stride 4KB
    }
}

__global__ __launch_bounds__(NTHR, 2) void fa_mma_kernel(
    const float* __restrict__ q,
    const float* __restrict__ dsq, const float* __restrict__ dsk, const float* __restrict__ dsv,
    const float* __restrict__ qss, const float* __restrict__ qso, const float* __restrict__ dss,
    float* __restrict__ out, float* __restrict__ amax_tail)
{
    extern __shared__ char smem[];
    const uint32_t sb = smem_u32(smem);
    float* redf = (float*)(smem + RED_OFF);

    const int t = threadIdx.x, w = t >> 5, lane = t & 31;
    const int g = lane >> 2, tig = lane & 3;
    const int subm = lane >> 3;
    const int a_r = (lane & 7) + ((subm & 1) << 3);
    const int a_c = ((subm >> 1) << 3);
    const int b_r = (lane & 7) + ((subm >> 1) << 3);
    const int b_c = ((subm & 1) << 3);

    const int qt = (gridDim.x - 1) - blockIdx.x;          // heavy tiles first
    const int bh = blockIdx.y;
    const size_t base = (size_t)bh * SEQ * HD;
    const int q0 = qt * BM;

    const float qk_scale = dsq[0] * dsk[0] * 0.125f * LOG2E;   // ex2 domain
    const float pv_scale = qss[0] * dss[0] * dsv[0];
    const float o_scale  = qso[0];

    // prefetch tile 0 first, then convert Q
    issue_tile(sb + STG_OFF, bh, 0, t);
    CP_COMMIT();

    for (int i = t; i < BM * (HD / 4); i += NTHR) {
        int r = i >> 4, c = (i & 15) * 4;
        float4 val = *(const float4*)(q + base + (size_t)(q0 + r) * HD + c);
        val.x *= qk_scale; val.y *= qk_scale; val.z *= qk_scale; val.w *= qk_scale;
        uint32_t h01 = packhf(val.x, val.y), h23 = packhf(val.z, val.w);
        float2 f01 = unpackhf(h01), f23 = unpackhf(h23);
        uint32_t l01 = packhf(val.x - f01.x, val.y - f01.y);
        uint32_t l23 = packhf(val.z - f23.x, val.w - f23.y);
        *(uint2*)(smem + QHI_OFF + r * RB + c * 2) = make_uint2(h01, h23);
        *(uint2*)(smem + QLO_OFF + r * RB + c * 2) = make_uint2(l01, l23);
    }

    float o_acc[8][4];
    #pragma unroll
    for (int nb = 0; nb < 8; nb++)
        #pragma unroll
        for (int j = 0; j < 4; j++) o_acc[nb][j] = 0.0f;
    float m0 = -1e30f, m1 = -1e30f, l0 = 0.0f, l1 = 0.0f;

    const int row_hi = q0 + w * 16 + 15;
    const int n_tiles = 2 * qt + 2;

    for (int kt = 0; kt < n_tiles; kt++) {
        const int n0 = kt * BN;
        CP_WAIT0();
        __syncthreads();
        if (kt + 1 < n_tiles) {
            issue_tile(sb + STG_OFF + ((kt + 1) & 1) * STG_SZ, bh, n0 + BN, t);
            CP_COMMIT();
        }
        const uint32_t stg = sb + STG_OFF + (kt & 1) * STG_SZ;

        const bool active = (n0 <= row_hi);
        if (active) {
            // ---- S = Q K^T : 2-pass fp16 (Qhi*Khi + Qlo*Khi) ----
            float s[8][4];
            #pragma unroll
            for (int nb = 0; nb < 8; nb++)
                #pragma unroll
                for (int j = 0; j < 4; j++) s[nb][j] = 0.0f;

            #pragma unroll
            for (int kb = 0; kb < 4; kb++) {
                uint32_t ah[4], al[4], b[4];
                uint32_t abase = sb + (uint32_t)((w * 16 + a_r) * RB + (kb * 16 + a_c) * 2);
                ldsm4(ah, abase + QHI_OFF);
                ldsm4(al, abase + QLO_OFF);
                #pragma unroll
                for (int np = 0; np < 4; np++) {
                    uint32_t bbase = stg + (uint32_t)((np * 16 + b_r) * RB + (kb * 16 + b_c) * 2);
                    ldsm4(b, bbase);                    // KHI
                    mma16816(s[2 * np],     ah, b[0], b[1]);
                    mma16816(s[2 * np + 1], ah, b[2], b[3]);
                    mma16816(s[2 * np],     al, b[0], b[1]);
                    mma16816(s[2 * np + 1], al, b[2], b[3]);
                }
            }

            // ---- causal mask ----
            if (n0 + BN - 1 > q0 + w * 16) {
                const int r0g = q0 + w * 16 + g, r1g = r0g + 8;
                #pragma unroll
                for (int nb = 0; nb < 8; nb++) {
                    const int c0 = n0 + nb * 8 + tig * 2;
                    if (c0 > r0g)     s[nb][0] = -1e30f;
                    if (c0 + 1 > r0g) s[nb][1] = -1e30f;
                    if (c0 > r1g)     s[nb][2] = -1e30f;
                    if (c0 + 1 > r1g) s[nb][3] = -1e30f;
                }
            }

            // ---- online softmax (base-2 domain) ----
            float mx0 = -1e30f, mx1 = -1e30f;
            #pragma unroll
            for (int nb = 0; nb < 8; nb++) {
                mx0 = fmaxf(mx0, fmaxf(s[nb][0], s[nb][1]));
                mx1 = fmaxf(mx1, fmaxf(s[nb][2], s[nb][3]));
            }
            mx0 = fmaxf(mx0, __shfl_xor_sync(0xffffffffu, mx0, 1));
            mx0 = fmaxf(mx0, __shfl_xor_sync(0xffffffffu, mx0, 2));
            mx1 = fmaxf(mx1, __shfl_xor_sync(0xffffffffu, mx1, 1));
            mx1 = fmaxf(mx1, __shfl_xor_sync(0xffffffffu, mx1, 2));
            const float mn0 = fmaxf(m0, mx0), mn1 = fmaxf(m1, mx1);
            const float al0 = ex2(m0 - mn0), al1 = ex2(m1 - mn1);
            float sum0 = 0.0f, sum1 = 0.0f;
            #pragma unroll
            for (int nb = 0; nb < 8; nb++) {
                s[nb][0] = ex2(s[nb][0] - mn0); sum0 += s[nb][0];
                s[nb][1] = ex2(s[nb][1] - mn0); sum0 += s[nb][1];
                s[nb][2] = ex2(s[nb][2] - mn1); sum1 += s[nb][2];
                s[nb][3] = ex2(s[nb][3] - mn1); sum1 += s[nb][3];
            }
            sum0 += __shfl_xor_sync(0xffffffffu, sum0, 1);
            sum0 += __shfl_xor_sync(0xffffffffu, sum0, 2);
            sum1 += __shfl_xor_sync(0xffffffffu, sum1, 1);
            sum1 += __shfl_xor_sync(0xffffffffu, sum1, 2);
            l0 = l0 * al0 + sum0; l1 = l1 * al1 + sum1;
            m0 = mn0; m1 = mn1;
            #pragma unroll
            for (int nb = 0; nb < 8; nb++) {
                o_acc[nb][0] *= al0; o_acc[nb][1] *= al0;
                o_acc[nb][2] *= al1; o_acc[nb][3] *= al1;
            }

            // ---- O += P V : 2-pass fp16 (Phi*Vhi + Plo*Vhi) ----
            #pragma unroll
            for (int kb = 0; kb < 4; kb++) {
                uint32_t ah[4], al_[4], b[4];
                ah[0] = packhf(s[2 * kb][0], s[2 * kb][1]);
                ah[1] = packhf(s[2 * kb][2], s[2 * kb][3]);
                ah[2] = packhf(s[2 * kb + 1][0], s[2 * kb + 1][1]);
                ah[3] = packhf(s[2 * kb + 1][2], s[2 * kb + 1][3]);
                float2 u0 = unpackhf(ah[0]), u1 = unpackhf(ah[1]);
                float2 u2 = unpackhf(ah[2]), u3 = unpackhf(ah[3]);
                al_[0] = packhf(s[2 * kb][0] - u0.x, s[2 * kb][1] - u0.y);
                al_[1] = packhf(s[2 * kb][2] - u1.x, s[2 * kb][3] - u1.y);
                al_[2] = packhf(s[2 * kb + 1][0] - u2.x, s[2 * kb + 1][1] - u2.y);
                al_[3] = packhf(s[2 * kb + 1][2] - u3.x, s[2 * kb + 1][3] - u3.y);
                #pragma unroll
                for (int np = 0; np < 4; np++) {
                    uint32_t bbase = stg + 9216 +
                        (uint32_t)((np * 16 + b_r) * RB + (kb * 16 + b_c) * 2);
                    ldsm4(b, bbase);                    // VTHI
                    mma16816(o_acc[2 * np],     ah, b[0], b[1]);
                    mma16816(o_acc[2 * np + 1], ah, b[2], b[3]);
                    mma16816(o_acc[2 * np],     al_, b[0], b[1]);
                    mma16816(o_acc[2 * np + 1], al_, b[2], b[3]);
                }
            }
        }
    }

    // ---- epilogue ----
    const float il0 = 1.0f / l0, il1 = 1.0f / l1;
    float amax_s_loc = fmaxf(il0, il1);
    float amax_o_loc = 0.0f;
    const int r0g = q0 + w * 16 + g, r1g = r0g + 8;
    #pragma unroll
    for (int nb = 0; nb < 8; nb++) {
        float v0 = o_acc[nb][0] * il0 * pv_scale;
        float v1 = o_acc[nb][1] * il0 * pv_scale;
        float v2 = o_acc[nb][2] * il1 * pv_scale;
        float v3 = o_acc[nb][3] * il1 * pv_scale;
        amax_o_loc = fmaxf(amax_o_loc, fmaxf(fmaxf(fabsf(v0), fabsf(v1)),
                                             fmaxf(fabsf(v2), fabsf(v3))));
        const int c = nb * 8 + tig * 2;
        *(float2*)(out + base + (size_t)r0g * HD + c) = make_float2(v0 * o_scale, v1 * o_scale);
        *(float2*)(out + base + (size_t)r1g * HD + c) = make_float2(v2 * o_scale, v3 * o_scale);
    }

    #pragma unroll
    for (int msk = 16; msk >= 1; msk >>= 1) {
        amax_s_loc = fmaxf(amax_s_loc, __shfl_xor_sync(0xffffffffu, amax_s_loc, msk));
        amax_o_loc = fmaxf(amax_o_loc, __shfl_xor_sync(0xffffffffu, amax_o_loc, msk));
    }
    if (lane == 0) { redf[w] = amax_s_loc; redf[8 + w] = amax_o_loc; }
    __syncthreads();
    if (t == 0) {
        float as = redf[0], ao = redf[8];
        #pragma unroll
        for (int i = 1; i < 8; i++) { as = fmaxf(as, redf[i]); ao = fmaxf(ao, redf[8 + i]); }
        atomic_max_pos(&amax_tail[0], as);
        atomic_max_pos(&amax_tail[1], ao);
    }
}

extern "C" void kernel_launch(void* const* d_in, const int* in_sizes, int n_in,
                              void* d_out, int out_size) {
    const float* q   = (const float*)d_in[0];
    const float* k   = (const float*)d_in[1];
    const float* v   = (const float*)d_in[2];
    const float* dsq = (const float*)d_in[3];
    const float* dsk = (const float*)d_in[4];
    const float* dsv = (const float*)d_in[5];
    const float* qss = (const float*)d_in[6];
    const float* qso = (const float*)d_in[7];
    const float* dss = (const float*)d_in[8];
    float* out = (float*)d_out;
    float* tail = out + (out_size - 2);

    cudaFuncSetAttribute(fa_mma_kernel,
                         cudaFuncAttributeMaxDynamicSharedMemorySize, SMEM_TOTAL);

    init_amax_kernel<<<1, 1>>>(tail);
    prep_kernel<<<dim3(SEQ / 64, BH), 256>>>(k, v);

    dim3 grid(SEQ / BM, BH);                 // (16, 32)
    fa_mma_kernel<<<grid, NTHR, SMEM_TOTAL>>>(q, dsq, dsk, dsv, qss, qso, dss,
                                              out, tail);
}

// round 7
// speedup vs baseline: 19.4372x; 1.1128x over previous
#include <cuda_runtime.h>
#include <cuda_fp16.h>
#include <cstdint>
#include <math.h>

#define BH   32
#define SEQ  2048
#define HD   64
#define BM   128
#define BN   64
#define NTHR 256
#define LOG2E 1.4426950408889634f

#define RB   144                       // smem row bytes (128 data + 16 pad)
#define QHI_OFF 0
#define QLO_OFF 18432
#define STG_OFF 36864                  // two 18432B stages follow
#define STG_SZ  18432
// within a stage: KHI +0, VTHI +9216
#define RED_OFF (STG_OFF + 2 * STG_SZ) // 73728
#define SMEM_TOTAL (RED_OFF + 256)

// pre-converted operands (written by prep_kernel each launch)
__device__ __half g_khi[(size_t)BH * SEQ * HD];
__device__ __half g_vthi[(size_t)BH * HD * SEQ];   // [bh][d][n]

__device__ __forceinline__ void atomic_max_pos(float* addr, float v) {
    atomicMax(reinterpret_cast<unsigned int*>(addr), __float_as_uint(v));
}
__device__ __forceinline__ uint32_t smem_u32(const void* p) {
    uint32_t a;
    asm("{ .reg .u64 t; cvta.to.shared.u64 t, %1; cvt.u32.u64 %0, t; }" : "=r"(a) : "l"(p));
    return a;
}
__device__ __forceinline__ void ldsm4(uint32_t r[4], uint32_t addr) {
    asm volatile("ldmatrix.sync.aligned.m8n8.x4.shared.b16 {%0,%1,%2,%3}, [%4];"
                 : "=r"(r[0]), "=r"(r[1]), "=r"(r[2]), "=r"(r[3]) : "r"(addr));
}
__device__ __forceinline__ void mma16816(float d[4], const uint32_t a[4],
                                         uint32_t b0, uint32_t b1) {
    asm volatile("mma.sync.aligned.m16n8k16.row.col.f32.f16.f16.f32 "
                 "{%0,%1,%2,%3},{%4,%5,%6,%7},{%8,%9},{%0,%1,%2,%3};"
                 : "+f"(d[0]), "+f"(d[1]), "+f"(d[2]), "+f"(d[3])
                 : "r"(a[0]), "r"(a[1]), "r"(a[2]), "r"(a[3]), "r"(b0), "r"(b1));
}
__device__ __forceinline__ uint32_t packhf(float x, float y) {
    __half2 h = __float22half2_rn(make_float2(x, y));
    return *reinterpret_cast<uint32_t*>(&h);
}
__device__ __forceinline__ float2 unpackhf(uint32_t u) {
    return __half22float2(*reinterpret_cast<__half2*>(&u));
}
__device__ __forceinline__ float ex2(float x) {
    float r; asm("ex2.approx.f32 %0, %1;" : "=f"(r) : "f"(x)); return r;
}
__device__ __forceinline__ void cpasync16(uint32_t dst, const void* src) {
    asm volatile("cp.async.cg.shared.global [%0], [%1], 16;" :: "r"(dst), "l"(src) : "memory");
}
#define CP_COMMIT() asm volatile("cp.async.commit_group;" ::: "memory")
#define CP_WAIT0()  asm volatile("cp.async.wait_group 0;" ::: "memory")

// ---- pre-pass: K -> fp16, V -> V^T fp16; also zero the amax tail ----
__global__ __launch_bounds__(256) void prep_kernel(const float* __restrict__ k,
                                                   const float* __restrict__ v,
                                                   float* __restrict__ tail) {
    __shared__ float vs[64][65];
    const int n0 = blockIdx.x * 64;
    const int bh = blockIdx.y;
    const int t = threadIdx.x;
    if (blockIdx.x == 0 && blockIdx.y == 0 && t == 0) { tail[0] = 0.0f; tail[1] = 0.0f; }
    const size_t base = (size_t)bh * SEQ * HD;

    for (int i = t; i < 64 * 16; i += 256) {
        int r = i >> 4, c = (i & 15) * 4;
        size_t eo = base + (size_t)(n0 + r) * HD + c;
        float4 kk = *(const float4*)(k + eo);
        *(uint2*)((uint16_t*)g_khi + eo) =
            make_uint2(packhf(kk.x, kk.y), packhf(kk.z, kk.w));
        float4 vv = *(const float4*)(v + eo);
        vs[r][c] = vv.x; vs[r][c + 1] = vv.y; vs[r][c + 2] = vv.z; vs[r][c + 3] = vv.w;
    }
    __syncthreads();
    const int d = t >> 2;
    const int nn0 = (t & 3) * 16;
    const size_t vbase = ((size_t)bh * HD + d) * SEQ + n0;
    #pragma unroll
    for (int nb = 0; nb < 4; nb++) {
        int n = nn0 + nb * 4;
        *(uint2*)((uint16_t*)g_vthi + vbase + n) =
            make_uint2(packhf(vs[n][d], vs[n + 1][d]), packhf(vs[n + 2][d], vs[n + 3][d]));
    }
}

// async-load one 64-row K/V^T tile (fp16, pre-converted) into a smem stage
__device__ __forceinline__ void issue_tile(uint32_t stg, int bh, int n0, int t) {
    const char* skhi = (const char*)g_khi + ((size_t)bh * SEQ + n0) * HD * 2;
    const char* svhi = (const char*)g_vthi + ((size_t)bh * HD * SEQ + n0) * 2;
    #pragma unroll
    for (int j = 0; j < 2; j++) {
        int rid = (j << 8) + t;            // 0..511 chunks per region
        int r = rid >> 3, c16 = rid & 7;
        cpasync16(stg + r * RB + c16 * 16, skhi + rid * 16);               // K rows 128B
        cpasync16(stg + 9216 + r * RB + c16 * 16,
                  svhi + (size_t)r * (SEQ * 2) + c16 * 16);                // V^T stride 4KB
    }
}

__global__ __launch_bounds__(NTHR, 3) void fa_mma_kernel(
    const float* __restrict__ q,
    const float* __restrict__ dsq, const float* __restrict__ dsk, const float* __restrict__ dsv,
    const float* __restrict__ qss, const float* __restrict__ qso, const float* __restrict__ dss,
    float* __restrict__ out, float* __restrict__ amax_tail)
{
    extern __shared__ char smem[];
    const uint32_t sb = smem_u32(smem);
    float* redf = (float*)(smem + RED_OFF);

    const int t = threadIdx.x, w = t >> 5, lane = t & 31;
    const int g = lane >> 2, tig = lane & 3;
    const int subm = lane >> 3;
    const int a_r = (lane & 7) + ((subm & 1) << 3);
    const int a_c = ((subm >> 1) << 3);
    const int b_r = (lane & 7) + ((subm >> 1) << 3);
    const int b_c = ((subm & 1) << 3);

    const int qt = (gridDim.x - 1) - blockIdx.x;          // heavy tiles first
    const int bh = blockIdx.y;
    const size_t base = (size_t)bh * SEQ * HD;
    const int q0 = qt * BM;

    const float qk_scale = dsq[0] * dsk[0] * 0.125f * LOG2E;   // ex2 domain
    const float pv_scale = qss[0] * dss[0] * dsv[0];
    const float o_scale  = qso[0];

    // prefetch tile 0 first, then convert Q
    issue_tile(sb + STG_OFF, bh, 0, t);
    CP_COMMIT();

    for (int i = t; i < BM * (HD / 4); i += NTHR) {
        int r = i >> 4, c = (i & 15) * 4;
        float4 val = *(const float4*)(q + base + (size_t)(q0 + r) * HD + c);
        val.x *= qk_scale; val.y *= qk_scale; val.z *= qk_scale; val.w *= qk_scale;
        uint32_t h01 = packhf(val.x, val.y), h23 = packhf(val.z, val.w);
        float2 f01 = unpackhf(h01), f23 = unpackhf(h23);
        uint32_t l01 = packhf(val.x - f01.x, val.y - f01.y);
        uint32_t l23 = packhf(val.z - f23.x, val.w - f23.y);
        *(uint2*)(smem + QHI_OFF + r * RB + c * 2) = make_uint2(h01, h23);
        *(uint2*)(smem + QLO_OFF + r * RB + c * 2) = make_uint2(l01, l23);
    }

    float o_acc[8][4];
    #pragma unroll
    for (int nb = 0; nb < 8; nb++)
        #pragma unroll
        for (int j = 0; j < 4; j++) o_acc[nb][j] = 0.0f;
    float m0 = -1e30f, m1 = -1e30f, l0 = 0.0f, l1 = 0.0f;

    const int row_hi = q0 + w * 16 + 15;
    const int n_tiles = 2 * qt + 2;

    for (int kt = 0; kt < n_tiles; kt++) {
        const int n0 = kt * BN;
        CP_WAIT0();
        __syncthreads();
        if (kt + 1 < n_tiles) {
            issue_tile(sb + STG_OFF + ((kt + 1) & 1) * STG_SZ, bh, n0 + BN, t);
            CP_COMMIT();
        }
        const uint32_t stg = sb + STG_OFF + (kt & 1) * STG_SZ;

        const bool active = (n0 <= row_hi);
        if (active) {
            // ---- S = Q K^T : 2-pass fp16 (Qhi*Khi + Qlo*Khi) ----
            float s[8][4];
            #pragma unroll
            for (int nb = 0; nb < 8; nb++)
                #pragma unroll
                for (int j = 0; j < 4; j++) s[nb][j] = 0.0f;

            #pragma unroll
            for (int kb = 0; kb < 4; kb++) {
                uint32_t ah[4], al[4], b[4];
                uint32_t abase = sb + (uint32_t)((w * 16 + a_r) * RB + (kb * 16 + a_c) * 2);
                ldsm4(ah, abase + QHI_OFF);
                ldsm4(al, abase + QLO_OFF);
                #pragma unroll
                for (int np = 0; np < 4; np++) {
                    uint32_t bbase = stg + (uint32_t)((np * 16 + b_r) * RB + (kb * 16 + b_c) * 2);
                    ldsm4(b, bbase);                    // KHI
                    mma16816(s[2 * np],     ah, b[0], b[1]);
                    mma16816(s[2 * np + 1], ah, b[2], b[3]);
                    mma16816(s[2 * np],     al, b[0], b[1]);
                    mma16816(s[2 * np + 1], al, b[2], b[3]);
                }
            }

            // ---- causal mask ----
            if (n0 + BN - 1 > q0 + w * 16) {
                const int r0g = q0 + w * 16 + g, r1g = r0g + 8;
                #pragma unroll
                for (int nb = 0; nb < 8; nb++) {
                    const int c0 = n0 + nb * 8 + tig * 2;
                    if (c0 > r0g)     s[nb][0] = -1e30f;
                    if (c0 + 1 > r0g) s[nb][1] = -1e30f;
                    if (c0 > r1g)     s[nb][2] = -1e30f;
                    if (c0 + 1 > r1g) s[nb][3] = -1e30f;
                }
            }

            // ---- online softmax (base-2 domain) ----
            float mx0 = -1e30f, mx1 = -1e30f;
            #pragma unroll
            for (int nb = 0; nb < 8; nb++) {
                mx0 = fmaxf(mx0, fmaxf(s[nb][0], s[nb][1]));
                mx1 = fmaxf(mx1, fmaxf(s[nb][2], s[nb][3]));
            }
            mx0 = fmaxf(mx0, __shfl_xor_sync(0xffffffffu, mx0, 1));
            mx0 = fmaxf(mx0, __shfl_xor_sync(0xffffffffu, mx0, 2));
            mx1 = fmaxf(mx1, __shfl_xor_sync(0xffffffffu, mx1, 1));
            mx1 = fmaxf(mx1, __shfl_xor_sync(0xffffffffu, mx1, 2));
            const float mn0 = fmaxf(m0, mx0), mn1 = fmaxf(m1, mx1);
            const float al0 = ex2(m0 - mn0), al1 = ex2(m1 - mn1);
            float sum0 = 0.0f, sum1 = 0.0f;
            // pack P to fp16 fragments immediately (s dies here)
            uint32_t ph[16];
            #pragma unroll
            for (int nb = 0; nb < 8; nb++) {
                s[nb][0] = ex2(s[nb][0] - mn0); sum0 += s[nb][0];
                s[nb][1] = ex2(s[nb][1] - mn0); sum0 += s[nb][1];
                s[nb][2] = ex2(s[nb][2] - mn1); sum1 += s[nb][2];
                s[nb][3] = ex2(s[nb][3] - mn1); sum1 += s[nb][3];
                ph[nb * 2]     = packhf(s[nb][0], s[nb][1]);
                ph[nb * 2 + 1] = packhf(s[nb][2], s[nb][3]);
            }
            sum0 += __shfl_xor_sync(0xffffffffu, sum0, 1);
            sum0 += __shfl_xor_sync(0xffffffffu, sum0, 2);
            sum1 += __shfl_xor_sync(0xffffffffu, sum1, 1);
            sum1 += __shfl_xor_sync(0xffffffffu, sum1, 2);
            l0 = l0 * al0 + sum0; l1 = l1 * al1 + sum1;
            m0 = mn0; m1 = mn1;
            #pragma unroll
            for (int nb = 0; nb < 8; nb++) {
                o_acc[nb][0] *= al0; o_acc[nb][1] *= al0;
                o_acc[nb][2] *= al1; o_acc[nb][3] *= al1;
            }

            // ---- O += P V : single-pass fp16 (Phi*Vhi) ----
            #pragma unroll
            for (int kb = 0; kb < 4; kb++) {
                const uint32_t* ap = ph + kb * 4;     // {p(2kb)[0:1], p(2kb)[2:3], p(2kb+1)[0:1], p(2kb+1)[2:3]}
                uint32_t b[4];
                #pragma unroll
                for (int np = 0; np < 4; np++) {
                    uint32_t bbase = stg + 9216 +
                        (uint32_t)((np * 16 + b_r) * RB + (kb * 16 + b_c) * 2);
                    ldsm4(b, bbase);                    // VTHI
                    mma16816(o_acc[2 * np],     ap, b[0], b[1]);
                    mma16816(o_acc[2 * np + 1], ap, b[2], b[3]);
                }
            }
        }
    }

    // ---- epilogue ----
    const float il0 = 1.0f / l0, il1 = 1.0f / l1;
    float amax_s_loc = fmaxf(il0, il1);
    float amax_o_loc = 0.0f;
    const int r0g = q0 + w * 16 + g, r1g = r0g + 8;
    #pragma unroll
    for (int nb = 0; nb < 8; nb++) {
        float v0 = o_acc[nb][0] * il0 * pv_scale;
        float v1 = o_acc[nb][1] * il0 * pv_scale;
        float v2 = o_acc[nb][2] * il1 * pv_scale;
        float v3 = o_acc[nb][3] * il1 * pv_scale;
        amax_o_loc = fmaxf(amax_o_loc, fmaxf(fmaxf(fabsf(v0), fabsf(v1)),
                                             fmaxf(fabsf(v2), fabsf(v3))));
        const int c = nb * 8 + tig * 2;
        *(float2*)(out + base + (size_t)r0g * HD + c) = make_float2(v0 * o_scale, v1 * o_scale);
        *(float2*)(out + base + (size_t)r1g * HD + c) = make_float2(v2 * o_scale, v3 * o_scale);
    }

    #pragma unroll
    for (int msk = 16; msk >= 1; msk >>= 1) {
        amax_s_loc = fmaxf(amax_s_loc, __shfl_xor_sync(0xffffffffu, amax_s_loc, msk));
        amax_o_loc = fmaxf(amax_o_loc, __shfl_xor_sync(0xffffffffu, amax_o_loc, msk));
    }
    if (lane == 0) { redf[w] = amax_s_loc; redf[8 + w] = amax_o_loc; }
    __syncthreads();
    if (t == 0) {
        float as = redf[0], ao = redf[8];
        #pragma unroll
        for (int i = 1; i < 8; i++) { as = fmaxf(as, redf[i]); ao = fmaxf(ao, redf[8 + i]); }
        atomic_max_pos(&amax_tail[0], as);
        atomic_max_pos(&amax_tail[1], ao);
    }
}

extern "C" void kernel_launch(void* const* d_in, const int* in_sizes, int n_in,
                              void* d_out, int out_size) {
    const float* q   = (const float*)d_in[0];
    const float* k   = (const float*)d_in[1];
    const float* v   = (const float*)d_in[2];
    const float* dsq = (const float*)d_in[3];
    const float* dsk = (const float*)d_in[4];
    const float* dsv = (const float*)d_in[5];
    const float* qss = (const float*)d_in[6];
    const float* qso = (const float*)d_in[7];
    const float* dss = (const float*)d_in[8];
    float* out = (float*)d_out;
    float* tail = out + (out_size - 2);

    cudaFuncSetAttribute(fa_mma_kernel,
                         cudaFuncAttributeMaxDynamicSharedMemorySize, SMEM_TOTAL);

    prep_kernel<<<dim3(SEQ / 64, BH), 256>>>(k, v, tail);

    dim3 grid(SEQ / BM, BH);                 // (16, 32)
    fa_mma_kernel<<<grid, NTHR, SMEM_TOTAL>>>(q, dsq, dsk, dsv, qss, qso, dss,
                                              out, tail);
}

// round 8
// speedup vs baseline: 23.6885x; 1.2187x over previous
#include <cuda_runtime.h>
#include <cuda_fp16.h>
#include <cstdint>
#include <math.h>

#define BH   32
#define SEQ  2048
#define HD   64
#define BM   128
#define BN   64
#define NTHR 256
#define LOG2E 1.4426950408889634f

#define RB   144                       // smem row bytes (128 data + 16 pad)
#define QHI_OFF 0
#define STG_OFF 18432                  // two 18432B stages follow
#define STG_SZ  18432
// within a stage: KHI +0, VTHI +9216
#define RED_OFF (STG_OFF + 2 * STG_SZ) // 55296
#define SMEM_TOTAL (RED_OFF + 256)

// pre-converted operands (written by prep_kernel each launch)
__device__ __half g_khi[(size_t)BH * SEQ * HD];
__device__ __half g_vthi[(size_t)BH * HD * SEQ];   // [bh][d][n]

__device__ __forceinline__ void atomic_max_pos(float* addr, float v) {
    atomicMax(reinterpret_cast<unsigned int*>(addr), __float_as_uint(v));
}
__device__ __forceinline__ uint32_t smem_u32(const void* p) {
    uint32_t a;
    asm("{ .reg .u64 t; cvta.to.shared.u64 t, %1; cvt.u32.u64 %0, t; }" : "=r"(a) : "l"(p));
    return a;
}
__device__ __forceinline__ void ldsm4(uint32_t r[4], uint32_t addr) {
    asm volatile("ldmatrix.sync.aligned.m8n8.x4.shared.b16 {%0,%1,%2,%3}, [%4];"
                 : "=r"(r[0]), "=r"(r[1]), "=r"(r[2]), "=r"(r[3]) : "r"(addr));
}
__device__ __forceinline__ void mma16816(float d[4], const uint32_t a[4],
                                         uint32_t b0, uint32_t b1) {
    asm volatile("mma.sync.aligned.m16n8k16.row.col.f32.f16.f16.f32 "
                 "{%0,%1,%2,%3},{%4,%5,%6,%7},{%8,%9},{%0,%1,%2,%3};"
                 : "+f"(d[0]), "+f"(d[1]), "+f"(d[2]), "+f"(d[3])
                 : "r"(a[0]), "r"(a[1]), "r"(a[2]), "r"(a[3]), "r"(b0), "r"(b1));
}
__device__ __forceinline__ uint32_t packhf(float x, float y) {
    __half2 h = __float22half2_rn(make_float2(x, y));
    return *reinterpret_cast<uint32_t*>(&h);
}
__device__ __forceinline__ float ex2(float x) {
    float r; asm("ex2.approx.f32 %0, %1;" : "=f"(r) : "f"(x)); return r;
}
__device__ __forceinline__ void cpasync16(uint32_t dst, const void* src) {
    asm volatile("cp.async.cg.shared.global [%0], [%1], 16;" :: "r"(dst), "l"(src) : "memory");
}
#define CP_COMMIT() asm volatile("cp.async.commit_group;" ::: "memory")
#define CP_WAIT0()  asm volatile("cp.async.wait_group 0;" ::: "memory")

// ---- pre-pass: K -> fp16, V -> V^T fp16; also zero the amax tail ----
__global__ __launch_bounds__(256) void prep_kernel(const float* __restrict__ k,
                                                   const float* __restrict__ v,
                                                   float* __restrict__ tail) {
    __shared__ float vs[64][65];
    const int n0 = blockIdx.x * 64;
    const int bh = blockIdx.y;
    const int t = threadIdx.x;
    if (blockIdx.x == 0 && blockIdx.y == 0 && t == 0) { tail[0] = 0.0f; tail[1] = 0.0f; }
    const size_t base = (size_t)bh * SEQ * HD;

    for (int i = t; i < 64 * 16; i += 256) {
        int r = i >> 4, c = (i & 15) * 4;
        size_t eo = base + (size_t)(n0 + r) * HD + c;
        float4 kk = *(const float4*)(k + eo);
        *(uint2*)((uint16_t*)g_khi + eo) =
            make_uint2(packhf(kk.x, kk.y), packhf(kk.z, kk.w));
        float4 vv = *(const float4*)(v + eo);
        vs[r][c] = vv.x; vs[r][c + 1] = vv.y; vs[r][c + 2] = vv.z; vs[r][c + 3] = vv.w;
    }
    __syncthreads();
    const int d = t >> 2;
    const int nn0 = (t & 3) * 16;
    const size_t vbase = ((size_t)bh * HD + d) * SEQ + n0;
    #pragma unroll
    for (int nb = 0; nb < 4; nb++) {
        int n = nn0 + nb * 4;
        *(uint2*)((uint16_t*)g_vthi + vbase + n) =
            make_uint2(packhf(vs[n][d], vs[n + 1][d]), packhf(vs[n + 2][d], vs[n + 3][d]));
    }
}

// async-load one 64-row K/V^T tile (fp16, pre-converted) into a smem stage
__device__ __forceinline__ void issue_tile(uint32_t stg, int bh, int n0, int t) {
    const char* skhi = (const char*)g_khi + ((size_t)bh * SEQ + n0) * HD * 2;
    const char* svhi = (const char*)g_vthi + ((size_t)bh * HD * SEQ + n0) * 2;
    #pragma unroll
    for (int j = 0; j < 2; j++) {
        int rid = (j << 8) + t;            // 0..511 chunks per region
        int r = rid >> 3, c16 = rid & 7;
        cpasync16(stg + r * RB + c16 * 16, skhi + rid * 16);               // K rows 128B
        cpasync16(stg + 9216 + r * RB + c16 * 16,
                  svhi + (size_t)r * (SEQ * 2) + c16 * 16);                // V^T stride 4KB
    }
}

__global__ __launch_bounds__(NTHR, 3) void fa_mma_kernel(
    const float* __restrict__ q,
    const float* __restrict__ dsq, const float* __restrict__ dsk, const float* __restrict__ dsv,
    const float* __restrict__ qss, const float* __restrict__ qso, const float* __restrict__ dss,
    float* __restrict__ out, float* __restrict__ amax_tail)
{
    extern __shared__ char smem[];
    const uint32_t sb = smem_u32(smem);
    float* redf = (float*)(smem + RED_OFF);

    const int t = threadIdx.x, w = t >> 5, lane = t & 31;
    const int g = lane >> 2, tig = lane & 3;
    const int subm = lane >> 3;
    const int a_r = (lane & 7) + ((subm & 1) << 3);
    const int a_c = ((subm >> 1) << 3);
    const int b_r = (lane & 7) + ((subm >> 1) << 3);
    const int b_c = ((subm & 1) << 3);

    const int qt = (gridDim.x - 1) - blockIdx.x;          // heavy tiles first
    const int bh = blockIdx.y;
    const size_t base = (size_t)bh * SEQ * HD;
    const int q0 = qt * BM;

    const float qk_scale = dsq[0] * dsk[0] * 0.125f * LOG2E;   // ex2 domain
    const float pv_scale = qss[0] * dss[0] * dsv[0];
    const float o_scale  = qso[0];

    // prefetch tile 0 first, then convert Q
    issue_tile(sb + STG_OFF, bh, 0, t);
    CP_COMMIT();

    for (int i = t; i < BM * (HD / 4); i += NTHR) {
        int r = i >> 4, c = (i & 15) * 4;
        float4 val = *(const float4*)(q + base + (size_t)(q0 + r) * HD + c);
        val.x *= qk_scale; val.y *= qk_scale; val.z *= qk_scale; val.w *= qk_scale;
        *(uint2*)(smem + QHI_OFF + r * RB + c * 2) =
            make_uint2(packhf(val.x, val.y), packhf(val.z, val.w));
    }

    float o_acc[8][4];
    #pragma unroll
    for (int nb = 0; nb < 8; nb++)
        #pragma unroll
        for (int j = 0; j < 4; j++) o_acc[nb][j] = 0.0f;
    float m0 = -1e30f, m1 = -1e30f, l0 = 0.0f, l1 = 0.0f;

    const int row_hi = q0 + w * 16 + 15;
    const int n_tiles = 2 * qt + 2;

    for (int kt = 0; kt < n_tiles; kt++) {
        const int n0 = kt * BN;
        CP_WAIT0();
        __syncthreads();
        if (kt + 1 < n_tiles) {
            issue_tile(sb + STG_OFF + ((kt + 1) & 1) * STG_SZ, bh, n0 + BN, t);
            CP_COMMIT();
        }
        const uint32_t stg = sb + STG_OFF + (kt & 1) * STG_SZ;

        const bool active = (n0 <= row_hi);
        if (active) {
            // ---- S = Q K^T : single-pass fp16 ----
            float s[8][4];
            #pragma unroll
            for (int nb = 0; nb < 8; nb++)
                #pragma unroll
                for (int j = 0; j < 4; j++) s[nb][j] = 0.0f;

            #pragma unroll
            for (int kb = 0; kb < 4; kb++) {
                uint32_t ah[4], b[4];
                uint32_t abase = sb + (uint32_t)((w * 16 + a_r) * RB + (kb * 16 + a_c) * 2);
                ldsm4(ah, abase + QHI_OFF);
                #pragma unroll
                for (int np = 0; np < 4; np++) {
                    uint32_t bbase = stg + (uint32_t)((np * 16 + b_r) * RB + (kb * 16 + b_c) * 2);
                    ldsm4(b, bbase);                    // KHI
                    mma16816(s[2 * np],     ah, b[0], b[1]);
                    mma16816(s[2 * np + 1], ah, b[2], b[3]);
                }
            }

            // ---- causal mask ----
            if (n0 + BN - 1 > q0 + w * 16) {
                const int r0g = q0 + w * 16 + g, r1g = r0g + 8;
                #pragma unroll
                for (int nb = 0; nb < 8; nb++) {
                    const int c0 = n0 + nb * 8 + tig * 2;
                    if (c0 > r0g)     s[nb][0] = -1e30f;
                    if (c0 + 1 > r0g) s[nb][1] = -1e30f;
                    if (c0 > r1g)     s[nb][2] = -1e30f;
                    if (c0 + 1 > r1g) s[nb][3] = -1e30f;
                }
            }

            // ---- online softmax (base-2 domain) ----
            float mx0 = -1e30f, mx1 = -1e30f;
            #pragma unroll
            for (int nb = 0; nb < 8; nb++) {
                mx0 = fmaxf(mx0, fmaxf(s[nb][0], s[nb][1]));
                mx1 = fmaxf(mx1, fmaxf(s[nb][2], s[nb][3]));
            }
            mx0 = fmaxf(mx0, __shfl_xor_sync(0xffffffffu, mx0, 1));
            mx0 = fmaxf(mx0, __shfl_xor_sync(0xffffffffu, mx0, 2));
            mx1 = fmaxf(mx1, __shfl_xor_sync(0xffffffffu, mx1, 1));
            mx1 = fmaxf(mx1, __shfl_xor_sync(0xffffffffu, mx1, 2));
            const float mn0 = fmaxf(m0, mx0), mn1 = fmaxf(m1, mx1);
            const float al0 = ex2(m0 - mn0), al1 = ex2(m1 - mn1);
            float sum0 = 0.0f, sum1 = 0.0f;
            uint32_t ph[16];
            #pragma unroll
            for (int nb = 0; nb < 8; nb++) {
                s[nb][0] = ex2(s[nb][0] - mn0); sum0 += s[nb][0];
                s[nb][1] = ex2(s[nb][1] - mn0); sum0 += s[nb][1];
                s[nb][2] = ex2(s[nb][2] - mn1); sum1 += s[nb][2];
                s[nb][3] = ex2(s[nb][3] - mn1); sum1 += s[nb][3];
                ph[nb * 2]     = packhf(s[nb][0], s[nb][1]);
                ph[nb * 2 + 1] = packhf(s[nb][2], s[nb][3]);
            }
            sum0 += __shfl_xor_sync(0xffffffffu, sum0, 1);
            sum0 += __shfl_xor_sync(0xffffffffu, sum0, 2);
            sum1 += __shfl_xor_sync(0xffffffffu, sum1, 1);
            sum1 += __shfl_xor_sync(0xffffffffu, sum1, 2);
            l0 = l0 * al0 + sum0; l1 = l1 * al1 + sum1;
            m0 = mn0; m1 = mn1;
            #pragma unroll
            for (int nb = 0; nb < 8; nb++) {
                o_acc[nb][0] *= al0; o_acc[nb][1] *= al0;
                o_acc[nb][2] *= al1; o_acc[nb][3] *= al1;
            }

            // ---- O += P V : single-pass fp16 ----
            #pragma unroll
            for (int kb = 0; kb < 4; kb++) {
                const uint32_t* ap = ph + kb * 4;
                uint32_t b[4];
                #pragma unroll
                for (int np = 0; np < 4; np++) {
                    uint32_t bbase = stg + 9216 +
                        (uint32_t)((np * 16 + b_r) * RB + (kb * 16 + b_c) * 2);
                    ldsm4(b, bbase);                    // VTHI
                    mma16816(o_acc[2 * np],     ap, b[0], b[1]);
                    mma16816(o_acc[2 * np + 1], ap, b[2], b[3]);
                }
            }
        }
    }

    // ---- epilogue ----
    const float il0 = 1.0f / l0, il1 = 1.0f / l1;
    float amax_s_loc = fmaxf(il0, il1);
    float amax_o_loc = 0.0f;
    const int r0g = q0 + w * 16 + g, r1g = r0g + 8;
    #pragma unroll
    for (int nb = 0; nb < 8; nb++) {
        float v0 = o_acc[nb][0] * il0 * pv_scale;
        float v1 = o_acc[nb][1] * il0 * pv_scale;
        float v2 = o_acc[nb][2] * il1 * pv_scale;
        float v3 = o_acc[nb][3] * il1 * pv_scale;
        amax_o_loc = fmaxf(amax_o_loc, fmaxf(fmaxf(fabsf(v0), fabsf(v1)),
                                             fmaxf(fabsf(v2), fabsf(v3))));
        const int c = nb * 8 + tig * 2;
        *(float2*)(out + base + (size_t)r0g * HD + c) = make_float2(v0 * o_scale, v1 * o_scale);
        *(float2*)(out + base + (size_t)r1g * HD + c) = make_float2(v2 * o_scale, v3 * o_scale);
    }

    #pragma unroll
    for (int msk = 16; msk >= 1; msk >>= 1) {
        amax_s_loc = fmaxf(amax_s_loc, __shfl_xor_sync(0xffffffffu, amax_s_loc, msk));
        amax_o_loc = fmaxf(amax_o_loc, __shfl_xor_sync(0xffffffffu, amax_o_loc, msk));
    }
    if (lane == 0) { redf[w] = amax_s_loc; redf[8 + w] = amax_o_loc; }
    __syncthreads();
    if (t == 0) {
        float as = redf[0], ao = redf[8];
        #pragma unroll
        for (int i = 1; i < 8; i++) { as = fmaxf(as, redf[i]); ao = fmaxf(ao, redf[8 + i]); }
        atomic_max_pos(&amax_tail[0], as);
        atomic_max_pos(&amax_tail[1], ao);
    }
}

extern "C" void kernel_launch(void* const* d_in, const int* in_sizes, int n_in,
                              void* d_out, int out_size) {
    const float* q   = (const float*)d_in[0];
    const float* k   = (const float*)d_in[1];
    const float* v   = (const float*)d_in[2];
    const float* dsq = (const float*)d_in[3];
    const float* dsk = (const float*)d_in[4];
    const float* dsv = (const float*)d_in[5];
    const float* qss = (const float*)d_in[6];
    const float* qso = (const float*)d_in[7];
    const float* dss = (const float*)d_in[8];
    float* out = (float*)d_out;
    float* tail = out + (out_size - 2);

    cudaFuncSetAttribute(fa_mma_kernel,
                         cudaFuncAttributeMaxDynamicSharedMemorySize, SMEM_TOTAL);

    prep_kernel<<<dim3(SEQ / 64, BH), 256>>>(k, v, tail);

    dim3 grid(SEQ / BM, BH);                 // (16, 32)
    fa_mma_kernel<<<grid, NTHR, SMEM_TOTAL>>>(q, dsq, dsk, dsv, qss, qso, dss,
                                              out, tail);
}